// round 1
// baseline (speedup 1.0000x reference)
#include <cuda_runtime.h>
#include <math.h>

#define Bx 256
#define Sx 141
#define Vx 1000
#define Ex 256
#define Hx 512
#define G4H 2048   // 4*H

// Scratch (device globals — no runtime allocation allowed)
__device__ float g_emb_proj[Vx * G4H];        // embedding @ W_ih[:, :E]^T   (8 MB)
__device__ float g_const[Bx * G4H];           // enc @ W_ih[:, E:]^T + b_ih + b_hh (2 MB)
__device__ float g_c[Bx * Hx];                // cell state (in-place, t==0 special-cased)
__device__ float g_hs[(size_t)Sx * Bx * Hx];  // all hidden states [S,B,H] (~74 MB)

// ---------------------------------------------------------------------------
// Generic NT GEMM, 64x64 tile, 4x4 microtile: C[m,n] = sum_k A[m,k]*W[n, koff+k] (+biases)
// ---------------------------------------------------------------------------
__global__ __launch_bounds__(256) void gemm_nt64(
    const float* __restrict__ A, int lda,
    const float* __restrict__ W, int ldw, int koff,
    const float* __restrict__ bias0, const float* __restrict__ bias1,
    float* __restrict__ C, int ldc, int M, int N, int K)
{
    __shared__ float sA[16][64];
    __shared__ float sB[16][64];
    const int tid = threadIdx.x;
    const int tx = tid & 15;      // n micro
    const int ty = tid >> 4;      // m micro
    const int n0 = blockIdx.x * 64;
    const int m0 = blockIdx.y * 64;

    const int lr = tid >> 2;          // 0..63
    const int lk = (tid & 3) * 4;     // 0,4,8,12

    float acc[4][4];
#pragma unroll
    for (int i = 0; i < 4; i++)
#pragma unroll
        for (int j = 0; j < 4; j++) acc[i][j] = 0.f;

    for (int k0 = 0; k0 < K; k0 += 16) {
        int m = m0 + lr;
        float4 av = make_float4(0.f, 0.f, 0.f, 0.f);
        if (m < M) av = *(const float4*)&A[(size_t)m * lda + k0 + lk];
        sA[lk + 0][lr] = av.x; sA[lk + 1][lr] = av.y;
        sA[lk + 2][lr] = av.z; sA[lk + 3][lr] = av.w;

        int n = n0 + lr;
        float4 bv = make_float4(0.f, 0.f, 0.f, 0.f);
        if (n < N) bv = *(const float4*)&W[(size_t)n * ldw + koff + k0 + lk];
        sB[lk + 0][lr] = bv.x; sB[lk + 1][lr] = bv.y;
        sB[lk + 2][lr] = bv.z; sB[lk + 3][lr] = bv.w;

        __syncthreads();
#pragma unroll
        for (int k = 0; k < 16; k++) {
            float4 a = *(const float4*)&sA[k][ty * 4];
            float4 b = *(const float4*)&sB[k][tx * 4];
            float aa[4] = {a.x, a.y, a.z, a.w};
            float bb[4] = {b.x, b.y, b.z, b.w};
#pragma unroll
            for (int i = 0; i < 4; i++)
#pragma unroll
                for (int j = 0; j < 4; j++)
                    acc[i][j] = fmaf(aa[i], bb[j], acc[i][j]);
        }
        __syncthreads();
    }

#pragma unroll
    for (int i = 0; i < 4; i++) {
        int m = m0 + ty * 4 + i;
        if (m >= M) continue;
#pragma unroll
        for (int j = 0; j < 4; j++) {
            int n = n0 + tx * 4 + j;
            if (n >= N) continue;
            float v = acc[i][j];
            if (bias0) v += bias0[n];
            if (bias1) v += bias1[n];
            C[(size_t)m * ldc + n] = v;
        }
    }
}

// ---------------------------------------------------------------------------
// One LSTM step, fused: gates = emb_proj[tok] + const + h_{t-1} @ W_hh^T,
// then pointwise LSTM. Tile: 32 batch x 32 units, 4 gates per output.
// Reads h from g_hs row (t-1), writes h into g_hs row t. c in place.
// ---------------------------------------------------------------------------
__global__ __launch_bounds__(256) void lstm_step(
    const float* __restrict__ W_hh,
    const int* __restrict__ tok,
    int t)
{
    __shared__ float sh[32][33];        // [k][b]  (padded)
    __shared__ float sw[4][32][33];     // [gate][u][k] (padded)

    const int tid = threadIdx.x;
    const int tx = tid & 31;    // unit within tile
    const int ty = tid >> 5;    // 0..7 -> 4 batch rows each
    const int u0 = blockIdx.x * 32;
    const int b0 = blockIdx.y * 32;

    float acc[4][4];  // [batch i][gate g]
#pragma unroll
    for (int i = 0; i < 4; i++)
#pragma unroll
        for (int g = 0; g < 4; g++) acc[i][g] = 0.f;

    if (t > 0) {
        const float* __restrict__ hin = g_hs + (size_t)(t - 1) * Bx * Hx;
        const int wr = tid >> 3;          // 0..31
        const int wk = (tid & 7) * 4;     // 0..28

        for (int k0 = 0; k0 < Hx; k0 += 32) {
            float4 hv = *(const float4*)&hin[(size_t)(b0 + wr) * Hx + k0 + wk];
            sh[wk + 0][wr] = hv.x; sh[wk + 1][wr] = hv.y;
            sh[wk + 2][wr] = hv.z; sh[wk + 3][wr] = hv.w;
#pragma unroll
            for (int g = 0; g < 4; g++) {
                float4 wv = *(const float4*)&W_hh[(size_t)(g * Hx + u0 + wr) * Hx + k0 + wk];
                sw[g][wr][wk + 0] = wv.x; sw[g][wr][wk + 1] = wv.y;
                sw[g][wr][wk + 2] = wv.z; sw[g][wr][wk + 3] = wv.w;
            }
            __syncthreads();
#pragma unroll
            for (int k = 0; k < 32; k++) {
                float w0 = sw[0][tx][k];
                float w1 = sw[1][tx][k];
                float w2 = sw[2][tx][k];
                float w3 = sw[3][tx][k];
#pragma unroll
                for (int i = 0; i < 4; i++) {
                    float hvv = sh[k][ty * 4 + i];
                    acc[i][0] = fmaf(hvv, w0, acc[i][0]);
                    acc[i][1] = fmaf(hvv, w1, acc[i][1]);
                    acc[i][2] = fmaf(hvv, w2, acc[i][2]);
                    acc[i][3] = fmaf(hvv, w3, acc[i][3]);
                }
            }
            __syncthreads();
        }
    }

    const int u = u0 + tx;
    float* __restrict__ hout = g_hs + (size_t)t * Bx * Hx;
#pragma unroll
    for (int i = 0; i < 4; i++) {
        const int b = b0 + ty * 4 + i;
        const int tk = tok[b * Sx + t];
        const float* __restrict__ ep = g_emb_proj + (size_t)tk * G4H;
        const float* __restrict__ cs = g_const + (size_t)b * G4H;

        float gi = acc[i][0] + ep[0 * Hx + u] + cs[0 * Hx + u];
        float gf = acc[i][1] + ep[1 * Hx + u] + cs[1 * Hx + u];
        float gg = acc[i][2] + ep[2 * Hx + u] + cs[2 * Hx + u];
        float go = acc[i][3] + ep[3 * Hx + u] + cs[3 * Hx + u];

        float is = 1.f / (1.f + expf(-gi));
        float fs = 1.f / (1.f + expf(-gf));
        float gt = tanhf(gg);
        float os = 1.f / (1.f + expf(-go));

        float cprev = (t > 0) ? g_c[(size_t)b * Hx + u] : 0.f;
        float cn = fs * cprev + is * gt;
        float hn = os * tanhf(cn);

        g_c[(size_t)b * Hx + u] = cn;
        hout[(size_t)b * Hx + u] = hn;
    }
}

// ---------------------------------------------------------------------------
// Output GEMM: logits[b,s,v] = hs[s,b,:] . out_W[v,:] + out_b[v]
// M = S*B = 36096 (row m = s*256 + b), N = V = 1000, K = 512.
// 128x128 tile, 8x8 microtile.
// ---------------------------------------------------------------------------
__global__ __launch_bounds__(256) void out_gemm(
    const float* __restrict__ Wo,
    const float* __restrict__ bo,
    float* __restrict__ out)
{
    __shared__ float sA[16][128];
    __shared__ float sB[16][128];
    const int tid = threadIdx.x;
    const int tx = tid & 15;     // n micro (8 cols)
    const int ty = tid >> 4;     // m micro (8 rows)
    const int n0 = blockIdx.x * 128;
    const int m0 = blockIdx.y * 128;

    const int lr = tid >> 2;          // 0..63
    const int lk = (tid & 3) * 4;     // 0,4,8,12

    float acc[8][8];
#pragma unroll
    for (int i = 0; i < 8; i++)
#pragma unroll
        for (int j = 0; j < 8; j++) acc[i][j] = 0.f;

    for (int k0 = 0; k0 < Hx; k0 += 16) {
#pragma unroll
        for (int r = 0; r < 2; r++) {
            int row = lr + r * 64;
            int m = m0 + row;
            float4 av = *(const float4*)&g_hs[(size_t)m * Hx + k0 + lk];
            sA[lk + 0][row] = av.x; sA[lk + 1][row] = av.y;
            sA[lk + 2][row] = av.z; sA[lk + 3][row] = av.w;

            int n = n0 + row;
            float4 bv = make_float4(0.f, 0.f, 0.f, 0.f);
            if (n < Vx) bv = *(const float4*)&Wo[(size_t)n * Hx + k0 + lk];
            sB[lk + 0][row] = bv.x; sB[lk + 1][row] = bv.y;
            sB[lk + 2][row] = bv.z; sB[lk + 3][row] = bv.w;
        }
        __syncthreads();
#pragma unroll
        for (int k = 0; k < 16; k++) {
            float a[8], b[8];
            *(float4*)&a[0] = *(const float4*)&sA[k][ty * 8];
            *(float4*)&a[4] = *(const float4*)&sA[k][ty * 8 + 4];
            *(float4*)&b[0] = *(const float4*)&sB[k][tx * 8];
            *(float4*)&b[4] = *(const float4*)&sB[k][tx * 8 + 4];
#pragma unroll
            for (int i = 0; i < 8; i++)
#pragma unroll
                for (int j = 0; j < 8; j++)
                    acc[i][j] = fmaf(a[i], b[j], acc[i][j]);
        }
        __syncthreads();
    }

#pragma unroll
    for (int i = 0; i < 8; i++) {
        int m = m0 + ty * 8 + i;
        int s = m >> 8;        // B = 256
        int b = m & 255;
        float* __restrict__ orow = out + ((size_t)b * Sx + s) * Vx;
#pragma unroll
        for (int j = 0; j < 8; j++) {
            int n = n0 + tx * 8 + j;
            if (n < Vx) orow[n] = acc[i][j] + bo[n];
        }
    }
}

// ---------------------------------------------------------------------------
extern "C" void kernel_launch(void* const* d_in, const int* in_sizes, int n_in,
                              void* d_out, int out_size)
{
    const float* enc   = (const float*)d_in[0];   // [B, E]
    const int*   tok   = (const int*)  d_in[1];   // [B, S]
    const float* emb   = (const float*)d_in[2];   // [V, E]
    const float* W_ih  = (const float*)d_in[3];   // [4H, 2E]
    const float* W_hh  = (const float*)d_in[4];   // [4H, H]
    const float* b_ih  = (const float*)d_in[5];   // [4H]
    const float* b_hh  = (const float*)d_in[6];   // [4H]
    // d_in[7..9]: attn_W, attn_b, v_w -- provably unused (softmax over 1 pos)
    const float* out_W = (const float*)d_in[10];  // [V, H]
    const float* out_b = (const float*)d_in[11];  // [V]
    float* out = (float*)d_out;                   // [B, S, V]

    float *p_emb_proj = nullptr, *p_const = nullptr;
    cudaGetSymbolAddress((void**)&p_emb_proj, g_emb_proj);
    cudaGetSymbolAddress((void**)&p_const, g_const);

    // 1) emb_proj[V, 4H] = embedding @ W_ih[:, :E]^T
    {
        dim3 grid(G4H / 64, (Vx + 63) / 64);
        gemm_nt64<<<grid, 256>>>(emb, Ex, W_ih, 2 * Ex, 0,
                                 nullptr, nullptr,
                                 p_emb_proj, G4H, Vx, G4H, Ex);
    }
    // 2) const[B, 4H] = enc @ W_ih[:, E:]^T + b_ih + b_hh
    {
        dim3 grid(G4H / 64, Bx / 64);
        gemm_nt64<<<grid, 256>>>(enc, Ex, W_ih, 2 * Ex, Ex,
                                 b_ih, b_hh,
                                 p_const, G4H, Bx, G4H, Ex);
    }
    // 3) 141 sequential LSTM steps
    {
        dim3 grid(Hx / 32, Bx / 32);   // 16 x 8 = 128 blocks (one wave)
        for (int t = 0; t < Sx; t++)
            lstm_step<<<grid, 256>>>(W_hh, tok, t);
    }
    // 4) logits = hs @ out_W^T + out_b
    {
        dim3 grid((Vx + 127) / 128, (Sx * Bx) / 128);  // 8 x 282
        out_gemm<<<grid, 256>>>(out_W, out_b, out);
    }
}

// round 2
// speedup vs baseline: 1.0274x; 1.0274x over previous
#include <cuda_runtime.h>
#include <math.h>

#define Bx 256
#define Sx 141
#define Vx 1000
#define Ex 256
#define Hx 512
#define G4H 2048   // 4*H

// Scratch (device globals — no runtime allocation allowed)
__device__ float g_emb_proj[Vx * G4H];        // embedding @ W_ih[:, :E]^T   (8 MB)
__device__ float g_const[Bx * G4H];           // enc @ W_ih[:, E:]^T + b_ih + b_hh (2 MB)
__device__ float g_c[Bx * Hx];                // cell state (in-place, t==0 special-cased)
__device__ float g_hs[(size_t)Sx * Bx * Hx];  // all hidden states [S,B,H] (~74 MB)
__device__ float g_wt[Hx * Hx * 4];           // W_hh transposed to [unit][k][gate] (4 MB)

// ---------------------------------------------------------------------------
// Generic NT GEMM, 64x64 tile, 4x4 microtile (prep only, tiny)
// ---------------------------------------------------------------------------
__global__ __launch_bounds__(256) void gemm_nt64(
    const float* __restrict__ A, int lda,
    const float* __restrict__ W, int ldw, int koff,
    const float* __restrict__ bias0, const float* __restrict__ bias1,
    float* __restrict__ C, int ldc, int M, int N, int K)
{
    __shared__ float sA[16][64];
    __shared__ float sB[16][64];
    const int tid = threadIdx.x;
    const int tx = tid & 15;
    const int ty = tid >> 4;
    const int n0 = blockIdx.x * 64;
    const int m0 = blockIdx.y * 64;

    const int lr = tid >> 2;
    const int lk = (tid & 3) * 4;

    float acc[4][4];
#pragma unroll
    for (int i = 0; i < 4; i++)
#pragma unroll
        for (int j = 0; j < 4; j++) acc[i][j] = 0.f;

    for (int k0 = 0; k0 < K; k0 += 16) {
        int m = m0 + lr;
        float4 av = make_float4(0.f, 0.f, 0.f, 0.f);
        if (m < M) av = *(const float4*)&A[(size_t)m * lda + k0 + lk];
        sA[lk + 0][lr] = av.x; sA[lk + 1][lr] = av.y;
        sA[lk + 2][lr] = av.z; sA[lk + 3][lr] = av.w;

        int n = n0 + lr;
        float4 bv = make_float4(0.f, 0.f, 0.f, 0.f);
        if (n < N) bv = *(const float4*)&W[(size_t)n * ldw + koff + k0 + lk];
        sB[lk + 0][lr] = bv.x; sB[lk + 1][lr] = bv.y;
        sB[lk + 2][lr] = bv.z; sB[lk + 3][lr] = bv.w;

        __syncthreads();
#pragma unroll
        for (int k = 0; k < 16; k++) {
            float4 a = *(const float4*)&sA[k][ty * 4];
            float4 b = *(const float4*)&sB[k][tx * 4];
            float aa[4] = {a.x, a.y, a.z, a.w};
            float bb[4] = {b.x, b.y, b.z, b.w};
#pragma unroll
            for (int i = 0; i < 4; i++)
#pragma unroll
                for (int j = 0; j < 4; j++)
                    acc[i][j] = fmaf(aa[i], bb[j], acc[i][j]);
        }
        __syncthreads();
    }

#pragma unroll
    for (int i = 0; i < 4; i++) {
        int m = m0 + ty * 4 + i;
        if (m >= M) continue;
#pragma unroll
        for (int j = 0; j < 4; j++) {
            int n = n0 + tx * 4 + j;
            if (n >= N) continue;
            float v = acc[i][j];
            if (bias0) v += bias0[n];
            if (bias1) v += bias1[n];
            C[(size_t)m * ldc + n] = v;
        }
    }
}

// ---------------------------------------------------------------------------
// Transpose W_hh [4H, H] -> g_wt [unit][k][gate]: wt[(u*512+k)*4+g] = W[g*512+u][k]
// ---------------------------------------------------------------------------
__global__ __launch_bounds__(256) void transpose_whh(const float* __restrict__ W)
{
    int i = blockIdx.x * 256 + threadIdx.x;   // over 512*512 (u,k) pairs
    int u = i >> 9;
    int k = i & 511;
    float4 v;
    v.x = W[(size_t)(0 * Hx + u) * Hx + k];
    v.y = W[(size_t)(1 * Hx + u) * Hx + k];
    v.z = W[(size_t)(2 * Hx + u) * Hx + k];
    v.w = W[(size_t)(3 * Hx + u) * Hx + k];
    *(float4*)&g_wt[(size_t)i * 4] = v;
}

// ---------------------------------------------------------------------------
// LSTM step v2. Grid 128 blocks x 256 threads.
// Block owns 256 batches x 4 units x 4 gates. Thread: 4 batches x 1 unit x 4 gates.
// W slice (32KB) in smem for the whole step; H double-buffered 16-k tiles.
// ---------------------------------------------------------------------------
#define SWU 2052              // padded unit stride in sw (floats): 512*4 + 4
#define HROW 260              // padded batch-row stride in hb (floats)
#define HBUF (16 * HROW)
#define SMEM_FLOATS (4 * SWU + 2 * HBUF)

__global__ __launch_bounds__(256) void lstm_step2(
    const int* __restrict__ tok, int t)
{
    extern __shared__ float smem[];
    float* sw = smem;                 // [4 units][512 k][4 gates] padded
    float* hb = smem + 4 * SWU;       // 2 x [16 k][260 batches-padded]

    const int tid = threadIdx.x;
    const int uu = tid & 3;           // unit within tile
    const int bg = tid >> 2;          // batch group 0..63
    const int u0 = blockIdx.x * 4;

    float acc[4][4];
#pragma unroll
    for (int i = 0; i < 4; i++)
#pragma unroll
        for (int g = 0; g < 4; g++) acc[i][g] = 0.f;

    if (t > 0) {
        // ---- stage W slice: 2048 float4 (u0..u0+3, all k, all gates) ----
        {
            const float4* src = (const float4*)&g_wt[(size_t)u0 * Hx * 4];
#pragma unroll
            for (int r = 0; r < 8; r++) {
                int i = r * 256 + tid;         // 0..2047
                int cu = i >> 9;
                int rem = i & 511;
                float4 v = src[i];
                *(float4*)&sw[cu * SWU + rem * 4] = v;
            }
        }

        const float* __restrict__ hin = g_hs + (size_t)(t - 1) * Bx * Hx;
        const int lb = tid >> 2;      // 0..63 row-in-chunk
        const int lj = tid & 3;       // 16B segment within 64B k-tile row

        // ---- preload tile 0 ----
        float4 pf[4];
#pragma unroll
        for (int it = 0; it < 4; it++)
            pf[it] = *(const float4*)&hin[(size_t)(it * 64 + lb) * Hx + lj * 4];
        {
            float* hb0 = hb;
#pragma unroll
            for (int it = 0; it < 4; it++) {
                int b = it * 64 + lb;
                hb0[(lj * 4 + 0) * HROW + b] = pf[it].x;
                hb0[(lj * 4 + 1) * HROW + b] = pf[it].y;
                hb0[(lj * 4 + 2) * HROW + b] = pf[it].z;
                hb0[(lj * 4 + 3) * HROW + b] = pf[it].w;
            }
        }
        __syncthreads();

        const float* wbase = sw + uu * SWU;

        for (int kt = 0; kt < 32; kt++) {
            const float* cur = hb + (kt & 1) * HBUF;
            float* nxt = hb + ((kt + 1) & 1) * HBUF;
            if (kt < 31) {
                int k0 = (kt + 1) * 16;
#pragma unroll
                for (int it = 0; it < 4; it++)
                    pf[it] = *(const float4*)&hin[(size_t)(it * 64 + lb) * Hx + k0 + lj * 4];
            }
            const float* hbase = cur + bg * 4;
            const float* wk = wbase + kt * 16 * 4;
#pragma unroll
            for (int k = 0; k < 16; k++) {
                float4 wv = *(const float4*)&wk[k * 4];
                float4 hv = *(const float4*)&hbase[k * HROW];
                acc[0][0] = fmaf(hv.x, wv.x, acc[0][0]);
                acc[0][1] = fmaf(hv.x, wv.y, acc[0][1]);
                acc[0][2] = fmaf(hv.x, wv.z, acc[0][2]);
                acc[0][3] = fmaf(hv.x, wv.w, acc[0][3]);
                acc[1][0] = fmaf(hv.y, wv.x, acc[1][0]);
                acc[1][1] = fmaf(hv.y, wv.y, acc[1][1]);
                acc[1][2] = fmaf(hv.y, wv.z, acc[1][2]);
                acc[1][3] = fmaf(hv.y, wv.w, acc[1][3]);
                acc[2][0] = fmaf(hv.z, wv.x, acc[2][0]);
                acc[2][1] = fmaf(hv.z, wv.y, acc[2][1]);
                acc[2][2] = fmaf(hv.z, wv.z, acc[2][2]);
                acc[2][3] = fmaf(hv.z, wv.w, acc[2][3]);
                acc[3][0] = fmaf(hv.w, wv.x, acc[3][0]);
                acc[3][1] = fmaf(hv.w, wv.y, acc[3][1]);
                acc[3][2] = fmaf(hv.w, wv.z, acc[3][2]);
                acc[3][3] = fmaf(hv.w, wv.w, acc[3][3]);
            }
            if (kt < 31) {
                __syncthreads();
#pragma unroll
                for (int it = 0; it < 4; it++) {
                    int b = it * 64 + lb;
                    nxt[(lj * 4 + 0) * HROW + b] = pf[it].x;
                    nxt[(lj * 4 + 1) * HROW + b] = pf[it].y;
                    nxt[(lj * 4 + 2) * HROW + b] = pf[it].z;
                    nxt[(lj * 4 + 3) * HROW + b] = pf[it].w;
                }
                __syncthreads();
            }
        }
    }

    // ---- pointwise LSTM epilogue ----
    const int u = u0 + uu;
    float* __restrict__ hout = g_hs + (size_t)t * Bx * Hx;
#pragma unroll
    for (int i = 0; i < 4; i++) {
        const int b = bg * 4 + i;
        const int tk = tok[b * Sx + t];
        const float* __restrict__ ep = g_emb_proj + (size_t)tk * G4H;
        const float* __restrict__ cs = g_const + (size_t)b * G4H;

        float gi = acc[i][0] + ep[0 * Hx + u] + cs[0 * Hx + u];
        float gf = acc[i][1] + ep[1 * Hx + u] + cs[1 * Hx + u];
        float gg = acc[i][2] + ep[2 * Hx + u] + cs[2 * Hx + u];
        float go = acc[i][3] + ep[3 * Hx + u] + cs[3 * Hx + u];

        float is = 1.f / (1.f + expf(-gi));
        float fs = 1.f / (1.f + expf(-gf));
        float gt = tanhf(gg);
        float os = 1.f / (1.f + expf(-go));

        float cprev = (t > 0) ? g_c[(size_t)b * Hx + u] : 0.f;
        float cn = fs * cprev + is * gt;
        float hn = os * tanhf(cn);

        g_c[(size_t)b * Hx + u] = cn;
        hout[(size_t)b * Hx + u] = hn;
    }
}

// ---------------------------------------------------------------------------
// Output GEMM: logits[b,s,v] = hs[s,b,:] . out_W[v,:] + out_b[v]
// M = S*B = 36096, N = V = 1000, K = 512. 128x128 tile, 8x8 micro, double-buffered.
// ---------------------------------------------------------------------------
__global__ __launch_bounds__(256) void out_gemm(
    const float* __restrict__ Wo,
    const float* __restrict__ bo,
    float* __restrict__ out)
{
    __shared__ float sA[2][16][128];
    __shared__ float sB[2][16][128];
    const int tid = threadIdx.x;
    const int tx = tid & 15;
    const int ty = tid >> 4;
    const int n0 = blockIdx.x * 128;
    const int m0 = blockIdx.y * 128;

    const int lr = tid >> 2;
    const int lk = (tid & 3) * 4;

    float acc[8][8];
#pragma unroll
    for (int i = 0; i < 8; i++)
#pragma unroll
        for (int j = 0; j < 8; j++) acc[i][j] = 0.f;

    float4 pa[2], pb[2];
    // preload tile 0
#pragma unroll
    for (int r = 0; r < 2; r++) {
        int row = lr + r * 64;
        pa[r] = *(const float4*)&g_hs[(size_t)(m0 + row) * Hx + lk];
        int n = n0 + row;
        pb[r] = make_float4(0.f, 0.f, 0.f, 0.f);
        if (n < Vx) pb[r] = *(const float4*)&Wo[(size_t)n * Hx + lk];
    }
#pragma unroll
    for (int r = 0; r < 2; r++) {
        int row = lr + r * 64;
        sA[0][lk + 0][row] = pa[r].x; sA[0][lk + 1][row] = pa[r].y;
        sA[0][lk + 2][row] = pa[r].z; sA[0][lk + 3][row] = pa[r].w;
        sB[0][lk + 0][row] = pb[r].x; sB[0][lk + 1][row] = pb[r].y;
        sB[0][lk + 2][row] = pb[r].z; sB[0][lk + 3][row] = pb[r].w;
    }
    __syncthreads();

    for (int kt = 0; kt < 32; kt++) {
        int cur = kt & 1;
        int nxt = cur ^ 1;
        if (kt < 31) {
            int k0 = (kt + 1) * 16;
#pragma unroll
            for (int r = 0; r < 2; r++) {
                int row = lr + r * 64;
                pa[r] = *(const float4*)&g_hs[(size_t)(m0 + row) * Hx + k0 + lk];
                int n = n0 + row;
                pb[r] = make_float4(0.f, 0.f, 0.f, 0.f);
                if (n < Vx) pb[r] = *(const float4*)&Wo[(size_t)n * Hx + k0 + lk];
            }
        }
#pragma unroll
        for (int k = 0; k < 16; k++) {
            float a[8], b[8];
            *(float4*)&a[0] = *(const float4*)&sA[cur][k][ty * 8];
            *(float4*)&a[4] = *(const float4*)&sA[cur][k][ty * 8 + 4];
            *(float4*)&b[0] = *(const float4*)&sB[cur][k][tx * 8];
            *(float4*)&b[4] = *(const float4*)&sB[cur][k][tx * 8 + 4];
#pragma unroll
            for (int i = 0; i < 8; i++)
#pragma unroll
                for (int j = 0; j < 8; j++)
                    acc[i][j] = fmaf(a[i], b[j], acc[i][j]);
        }
        if (kt < 31) {
            __syncthreads();
#pragma unroll
            for (int r = 0; r < 2; r++) {
                int row = lr + r * 64;
                sA[nxt][lk + 0][row] = pa[r].x; sA[nxt][lk + 1][row] = pa[r].y;
                sA[nxt][lk + 2][row] = pa[r].z; sA[nxt][lk + 3][row] = pa[r].w;
                sB[nxt][lk + 0][row] = pb[r].x; sB[nxt][lk + 1][row] = pb[r].y;
                sB[nxt][lk + 2][row] = pb[r].z; sB[nxt][lk + 3][row] = pb[r].w;
            }
            __syncthreads();
        }
    }

#pragma unroll
    for (int i = 0; i < 8; i++) {
        int m = m0 + ty * 8 + i;
        int s = m >> 8;        // B = 256
        int b = m & 255;
        float* __restrict__ orow = out + ((size_t)b * Sx + s) * Vx;
#pragma unroll
        for (int j = 0; j < 8; j++) {
            int n = n0 + tx * 8 + j;
            if (n < Vx) orow[n] = acc[i][j] + bo[n];
        }
    }
}

// ---------------------------------------------------------------------------
extern "C" void kernel_launch(void* const* d_in, const int* in_sizes, int n_in,
                              void* d_out, int out_size)
{
    const float* enc   = (const float*)d_in[0];   // [B, E]
    const int*   tok   = (const int*)  d_in[1];   // [B, S]
    const float* emb   = (const float*)d_in[2];   // [V, E]
    const float* W_ih  = (const float*)d_in[3];   // [4H, 2E]
    const float* W_hh  = (const float*)d_in[4];   // [4H, H]
    const float* b_ih  = (const float*)d_in[5];   // [4H]
    const float* b_hh  = (const float*)d_in[6];   // [4H]
    // d_in[7..9]: attn_W, attn_b, v_w -- provably unused (softmax over 1 pos)
    const float* out_W = (const float*)d_in[10];  // [V, H]
    const float* out_b = (const float*)d_in[11];  // [V]
    float* out = (float*)d_out;                   // [B, S, V]

    float *p_emb_proj = nullptr, *p_const = nullptr;
    cudaGetSymbolAddress((void**)&p_emb_proj, g_emb_proj);
    cudaGetSymbolAddress((void**)&p_const, g_const);

    static bool attr_set = false;
    if (!attr_set) {
        cudaFuncSetAttribute(lstm_step2, cudaFuncAttributeMaxDynamicSharedMemorySize,
                             SMEM_FLOATS * (int)sizeof(float));
        attr_set = true;
    }

    // 1) emb_proj[V, 4H] = embedding @ W_ih[:, :E]^T
    {
        dim3 grid(G4H / 64, (Vx + 63) / 64);
        gemm_nt64<<<grid, 256>>>(emb, Ex, W_ih, 2 * Ex, 0,
                                 nullptr, nullptr,
                                 p_emb_proj, G4H, Vx, G4H, Ex);
    }
    // 2) const[B, 4H] = enc @ W_ih[:, E:]^T + b_ih + b_hh
    {
        dim3 grid(G4H / 64, Bx / 64);
        gemm_nt64<<<grid, 256>>>(enc, Ex, W_ih, 2 * Ex, Ex,
                                 b_ih, b_hh,
                                 p_const, G4H, Bx, G4H, Ex);
    }
    // 2b) W_hh -> [unit][k][gate]
    transpose_whh<<<(Hx * Hx) / 256, 256>>>(W_hh);

    // 3) 141 sequential LSTM steps
    {
        size_t smem = SMEM_FLOATS * sizeof(float);
        for (int t = 0; t < Sx; t++)
            lstm_step2<<<128, 256, smem>>>(tok, t);
    }
    // 4) logits = hs @ out_W^T + out_b
    {
        dim3 grid((Vx + 127) / 128, (Sx * Bx) / 128);  // 8 x 282
        out_gemm<<<grid, 256>>>(out_W, out_b, out);
    }
}

// round 6
// speedup vs baseline: 1.1335x; 1.1033x over previous
#include <cuda_runtime.h>
#include <cuda_bf16.h>
#include <math.h>
#include <stdint.h>

#define Bx 256
#define Sx 141
#define Vx 1000
#define VP 1024    // V padded to 8x128 tiles
#define Ex 256
#define Hx 512
#define G4H 2048   // 4*H
#define Mtot (Sx * Bx)   // 36096

// ---------------- device scratch (no runtime allocation) -------------------
__device__ float g_emb_proj[Vx * G4H];
__device__ float g_const[Bx * G4H];
__device__ float g_c[Bx * Hx];
__device__ float g_hs[(size_t)Sx * Bx * Hx];
__device__ float g_wt[Hx * Hx * 4];
__device__ __nv_bfloat16 g_hs_hi[(size_t)Mtot * Hx];
__device__ __nv_bfloat16 g_hs_lo[(size_t)Mtot * Hx];
__device__ __nv_bfloat16 g_wo_hi[(size_t)VP * Hx];
__device__ __nv_bfloat16 g_wo_lo[(size_t)VP * Hx];

// ---------------- helpers ---------------------------------------------------
__device__ __forceinline__ uint32_t smem_u32(const void* p) {
    uint32_t a;
    asm("{ .reg .u64 t; cvta.to.shared.u64 t, %1; cvt.u32.u64 %0, t; }" : "=r"(a) : "l"(p));
    return a;
}
__device__ __forceinline__ void ldm_x4(uint32_t addr, uint32_t* r) {
    asm volatile("ldmatrix.sync.aligned.m8n8.x4.shared.b16 {%0,%1,%2,%3}, [%4];"
                 : "=r"(r[0]), "=r"(r[1]), "=r"(r[2]), "=r"(r[3]) : "r"(addr));
}
__device__ __forceinline__ void mma_bf16(float* d, const uint32_t* a, const uint32_t* b) {
    asm volatile(
        "mma.sync.aligned.m16n8k16.row.col.f32.bf16.bf16.f32 "
        "{%0,%1,%2,%3}, {%4,%5,%6,%7}, {%8,%9}, {%0,%1,%2,%3};"
        : "+f"(d[0]), "+f"(d[1]), "+f"(d[2]), "+f"(d[3])
        : "r"(a[0]), "r"(a[1]), "r"(a[2]), "r"(a[3]), "r"(b[0]), "r"(b[1]));
}

// ---------------------------------------------------------------------------
// Generic NT GEMM, 64x64 tile (prep only)
// ---------------------------------------------------------------------------
__global__ __launch_bounds__(256) void gemm_nt64(
    const float* __restrict__ A, int lda,
    const float* __restrict__ W, int ldw, int koff,
    const float* __restrict__ bias0, const float* __restrict__ bias1,
    float* __restrict__ C, int ldc, int M, int N, int K)
{
    __shared__ float sA[16][64];
    __shared__ float sB[16][64];
    const int tid = threadIdx.x;
    const int tx = tid & 15;
    const int ty = tid >> 4;
    const int n0 = blockIdx.x * 64;
    const int m0 = blockIdx.y * 64;
    const int lr = tid >> 2;
    const int lk = (tid & 3) * 4;

    float acc[4][4];
#pragma unroll
    for (int i = 0; i < 4; i++)
#pragma unroll
        for (int j = 0; j < 4; j++) acc[i][j] = 0.f;

    for (int k0 = 0; k0 < K; k0 += 16) {
        int m = m0 + lr;
        float4 av = make_float4(0.f, 0.f, 0.f, 0.f);
        if (m < M) av = *(const float4*)&A[(size_t)m * lda + k0 + lk];
        sA[lk + 0][lr] = av.x; sA[lk + 1][lr] = av.y;
        sA[lk + 2][lr] = av.z; sA[lk + 3][lr] = av.w;
        int n = n0 + lr;
        float4 bv = make_float4(0.f, 0.f, 0.f, 0.f);
        if (n < N) bv = *(const float4*)&W[(size_t)n * ldw + koff + k0 + lk];
        sB[lk + 0][lr] = bv.x; sB[lk + 1][lr] = bv.y;
        sB[lk + 2][lr] = bv.z; sB[lk + 3][lr] = bv.w;
        __syncthreads();
#pragma unroll
        for (int k = 0; k < 16; k++) {
            float4 a = *(const float4*)&sA[k][ty * 4];
            float4 b = *(const float4*)&sB[k][tx * 4];
            float aa[4] = {a.x, a.y, a.z, a.w};
            float bb[4] = {b.x, b.y, b.z, b.w};
#pragma unroll
            for (int i = 0; i < 4; i++)
#pragma unroll
                for (int j = 0; j < 4; j++)
                    acc[i][j] = fmaf(aa[i], bb[j], acc[i][j]);
        }
        __syncthreads();
    }
#pragma unroll
    for (int i = 0; i < 4; i++) {
        int m = m0 + ty * 4 + i;
        if (m >= M) continue;
#pragma unroll
        for (int j = 0; j < 4; j++) {
            int n = n0 + tx * 4 + j;
            if (n >= N) continue;
            float v = acc[i][j];
            if (bias0) v += bias0[n];
            if (bias1) v += bias1[n];
            C[(size_t)m * ldc + n] = v;
        }
    }
}

// ---------------------------------------------------------------------------
__global__ __launch_bounds__(256) void transpose_whh(const float* __restrict__ W)
{
    int i = blockIdx.x * 256 + threadIdx.x;
    int u = i >> 9;
    int k = i & 511;
    float4 v;
    v.x = W[(size_t)(0 * Hx + u) * Hx + k];
    v.y = W[(size_t)(1 * Hx + u) * Hx + k];
    v.z = W[(size_t)(2 * Hx + u) * Hx + k];
    v.w = W[(size_t)(3 * Hx + u) * Hx + k];
    *(float4*)&g_wt[(size_t)i * 4] = v;
}

// ---------------------------------------------------------------------------
// LSTM step (unchanged)
// ---------------------------------------------------------------------------
#define SWU 2052
#define HROW 260
#define HBUF (16 * HROW)
#define SMEM_FLOATS (4 * SWU + 2 * HBUF)

__global__ __launch_bounds__(256) void lstm_step2(const int* __restrict__ tok, int t)
{
    extern __shared__ float smem[];
    float* sw = smem;
    float* hb = smem + 4 * SWU;

    const int tid = threadIdx.x;
    const int uu = tid & 3;
    const int bg = tid >> 2;
    const int u0 = blockIdx.x * 4;

    float acc[4][4];
#pragma unroll
    for (int i = 0; i < 4; i++)
#pragma unroll
        for (int g = 0; g < 4; g++) acc[i][g] = 0.f;

    if (t > 0) {
        {
            const float4* src = (const float4*)&g_wt[(size_t)u0 * Hx * 4];
#pragma unroll
            for (int r = 0; r < 8; r++) {
                int i = r * 256 + tid;
                int cu = i >> 9;
                int rem = i & 511;
                float4 v = src[i];
                *(float4*)&sw[cu * SWU + rem * 4] = v;
            }
        }
        const float* __restrict__ hin = g_hs + (size_t)(t - 1) * Bx * Hx;
        const int lb = tid >> 2;
        const int lj = tid & 3;

        float4 pf[4];
#pragma unroll
        for (int it = 0; it < 4; it++)
            pf[it] = *(const float4*)&hin[(size_t)(it * 64 + lb) * Hx + lj * 4];
        {
            float* hb0 = hb;
#pragma unroll
            for (int it = 0; it < 4; it++) {
                int b = it * 64 + lb;
                hb0[(lj * 4 + 0) * HROW + b] = pf[it].x;
                hb0[(lj * 4 + 1) * HROW + b] = pf[it].y;
                hb0[(lj * 4 + 2) * HROW + b] = pf[it].z;
                hb0[(lj * 4 + 3) * HROW + b] = pf[it].w;
            }
        }
        __syncthreads();

        const float* wbase = sw + uu * SWU;
        for (int kt = 0; kt < 32; kt++) {
            const float* cur = hb + (kt & 1) * HBUF;
            float* nxt = hb + ((kt + 1) & 1) * HBUF;
            if (kt < 31) {
                int k0 = (kt + 1) * 16;
#pragma unroll
                for (int it = 0; it < 4; it++)
                    pf[it] = *(const float4*)&hin[(size_t)(it * 64 + lb) * Hx + k0 + lj * 4];
            }
            const float* hbase = cur + bg * 4;
            const float* wk = wbase + kt * 16 * 4;
#pragma unroll
            for (int k = 0; k < 16; k++) {
                float4 wv = *(const float4*)&wk[k * 4];
                float4 hv = *(const float4*)&hbase[k * HROW];
                acc[0][0] = fmaf(hv.x, wv.x, acc[0][0]);
                acc[0][1] = fmaf(hv.x, wv.y, acc[0][1]);
                acc[0][2] = fmaf(hv.x, wv.z, acc[0][2]);
                acc[0][3] = fmaf(hv.x, wv.w, acc[0][3]);
                acc[1][0] = fmaf(hv.y, wv.x, acc[1][0]);
                acc[1][1] = fmaf(hv.y, wv.y, acc[1][1]);
                acc[1][2] = fmaf(hv.y, wv.z, acc[1][2]);
                acc[1][3] = fmaf(hv.y, wv.w, acc[1][3]);
                acc[2][0] = fmaf(hv.z, wv.x, acc[2][0]);
                acc[2][1] = fmaf(hv.z, wv.y, acc[2][1]);
                acc[2][2] = fmaf(hv.z, wv.z, acc[2][2]);
                acc[2][3] = fmaf(hv.z, wv.w, acc[2][3]);
                acc[3][0] = fmaf(hv.w, wv.x, acc[3][0]);
                acc[3][1] = fmaf(hv.w, wv.y, acc[3][1]);
                acc[3][2] = fmaf(hv.w, wv.z, acc[3][2]);
                acc[3][3] = fmaf(hv.w, wv.w, acc[3][3]);
            }
            if (kt < 31) {
                __syncthreads();
#pragma unroll
                for (int it = 0; it < 4; it++) {
                    int b = it * 64 + lb;
                    nxt[(lj * 4 + 0) * HROW + b] = pf[it].x;
                    nxt[(lj * 4 + 1) * HROW + b] = pf[it].y;
                    nxt[(lj * 4 + 2) * HROW + b] = pf[it].z;
                    nxt[(lj * 4 + 3) * HROW + b] = pf[it].w;
                }
                __syncthreads();
            }
        }
    }

    const int u = u0 + uu;
    float* __restrict__ hout = g_hs + (size_t)t * Bx * Hx;
#pragma unroll
    for (int i = 0; i < 4; i++) {
        const int b = bg * 4 + i;
        const int tk = tok[b * Sx + t];
        const float* __restrict__ ep = g_emb_proj + (size_t)tk * G4H;
        const float* __restrict__ cs = g_const + (size_t)b * G4H;

        float gi = acc[i][0] + ep[0 * Hx + u] + cs[0 * Hx + u];
        float gf = acc[i][1] + ep[1 * Hx + u] + cs[1 * Hx + u];
        float gg = acc[i][2] + ep[2 * Hx + u] + cs[2 * Hx + u];
        float go = acc[i][3] + ep[3 * Hx + u] + cs[3 * Hx + u];

        float is = 1.f / (1.f + expf(-gi));
        float fs = 1.f / (1.f + expf(-gf));
        float gt = tanhf(gg);
        float os = 1.f / (1.f + expf(-go));

        float cprev = (t > 0) ? g_c[(size_t)b * Hx + u] : 0.f;
        float cn = fs * cprev + is * gt;
        float hn = os * tanhf(cn);

        g_c[(size_t)b * Hx + u] = cn;
        hout[(size_t)b * Hx + u] = hn;
    }
}

// ---------------------------------------------------------------------------
// fp32 -> bf16 hi/lo split conversions
// ---------------------------------------------------------------------------
__global__ __launch_bounds__(256) void cvt_hs()
{
    size_t i = ((size_t)blockIdx.x * 256 + threadIdx.x) * 4;
    float4 v = *(const float4*)&g_hs[i];
    float x[4] = {v.x, v.y, v.z, v.w};
    __nv_bfloat16 hi[4], lo[4];
#pragma unroll
    for (int j = 0; j < 4; j++) {
        hi[j] = __float2bfloat16(x[j]);
        lo[j] = __float2bfloat16(x[j] - __bfloat162float(hi[j]));
    }
    *(uint2*)&g_hs_hi[i] = *(uint2*)hi;
    *(uint2*)&g_hs_lo[i] = *(uint2*)lo;
}

__global__ __launch_bounds__(256) void cvt_wo(const float* __restrict__ Wo)
{
    size_t i = ((size_t)blockIdx.x * 256 + threadIdx.x) * 4;
    int row = (int)(i >> 9);
    float x[4] = {0.f, 0.f, 0.f, 0.f};
    if (row < Vx) {
        float4 v = *(const float4*)&Wo[i];
        x[0] = v.x; x[1] = v.y; x[2] = v.z; x[3] = v.w;
    }
    __nv_bfloat16 hi[4], lo[4];
#pragma unroll
    for (int j = 0; j < 4; j++) {
        hi[j] = __float2bfloat16(x[j]);
        lo[j] = __float2bfloat16(x[j] - __bfloat162float(hi[j]));
    }
    *(uint2*)&g_wo_hi[i] = *(uint2*)hi;
    *(uint2*)&g_wo_lo[i] = *(uint2*)lo;
}

// ---------------------------------------------------------------------------
// Output GEMM with mma.sync bf16 (3-pass hi/lo split).
// CTA: 256 thr = 8 warps (4m x 2n). CTA tile 128m x 128n. Warp tile 32m x 64n.
// K staged 32-wide, double-buffered smem, 48 stages (3 passes x 512).
// smem rows padded to 40 bf16 (80B) -> conflict-free ldmatrix.
// ---------------------------------------------------------------------------
#define OG_PAD 40

__global__ __launch_bounds__(256) void out_gemm_mma(
    const float* __restrict__ bo, float* __restrict__ out)
{
    __shared__ __align__(16) __nv_bfloat16 sA[2][128][OG_PAD];
    __shared__ __align__(16) __nv_bfloat16 sB[2][128][OG_PAD];

    const int tid = threadIdx.x;
    const int wid = tid >> 5;
    const int lane = tid & 31;
    const int wm = wid & 3;          // warp m index (0..3)
    const int wn = wid >> 2;         // warp n index (0..1)
    const int n0 = blockIdx.x * 128;
    const int m0 = blockIdx.y * 128;

    const uint32_t sA_u = smem_u32(sA);
    const uint32_t sB_u = smem_u32(sB);
    const uint32_t bufStride = 128 * OG_PAD * 2;   // bytes per buffer

    float acc[2][8][4];
#pragma unroll
    for (int mt = 0; mt < 2; mt++)
#pragma unroll
        for (int nt = 0; nt < 8; nt++)
#pragma unroll
            for (int e = 0; e < 4; e++) acc[mt][nt][e] = 0.f;

    // ldmatrix lane addressing (bytes, within buffer)
    const uint32_t a_row = wm * 32 + (lane & 15);          // + mt*16
    const uint32_t a_colb = (lane >> 4) * 16;              // + kk*32
    const uint32_t b_row = wn * 64 + ((lane >> 3) >= 2 ? 8 : 0) + (lane & 7); // + np*16
    const uint32_t b_colb = ((lane >> 3) & 1) * 16;        // + kk*32

    // global load mapping: 2 segments per thread per matrix
    const int s0 = tid;            // seg ids: tid, tid+256 (512 total = 128 rows x 4 segs)
    const int r0g = s0 >> 2, c0g = s0 & 3;
    const int s1 = tid + 256;
    const int r1g = s1 >> 2, c1g = s1 & 3;

    float4 pa0, pa1, pb0, pb1;
    // ---- preload stage 0 (pass 0 = hi*hi, k0 = 0) ----
    pa0 = *(const float4*)&g_hs_hi[(size_t)(m0 + r0g) * Hx + c0g * 8];
    pa1 = *(const float4*)&g_hs_hi[(size_t)(m0 + r1g) * Hx + c1g * 8];
    pb0 = *(const float4*)&g_wo_hi[(size_t)(n0 + r0g) * Hx + c0g * 8];
    pb1 = *(const float4*)&g_wo_hi[(size_t)(n0 + r1g) * Hx + c1g * 8];
    *(float4*)&sA[0][r0g][c0g * 8] = pa0;
    *(float4*)&sA[0][r1g][c1g * 8] = pa1;
    *(float4*)&sB[0][r0g][c0g * 8] = pb0;
    *(float4*)&sB[0][r1g][c1g * 8] = pb1;
    __syncthreads();

    for (int st = 0; st < 48; st++) {
        const int cur = st & 1;
        const int nxt = cur ^ 1;
        if (st < 47) {
            const int p = (st + 1) >> 4;               // pass of next stage
            const int k0 = ((st + 1) & 15) * 32;
            const __nv_bfloat16* __restrict__ Asrc = (p == 1) ? g_hs_lo : g_hs_hi;
            const __nv_bfloat16* __restrict__ Bsrc = (p == 2) ? g_wo_lo : g_wo_hi;
            pa0 = *(const float4*)&Asrc[(size_t)(m0 + r0g) * Hx + k0 + c0g * 8];
            pa1 = *(const float4*)&Asrc[(size_t)(m0 + r1g) * Hx + k0 + c1g * 8];
            pb0 = *(const float4*)&Bsrc[(size_t)(n0 + r0g) * Hx + k0 + c0g * 8];
            pb1 = *(const float4*)&Bsrc[(size_t)(n0 + r1g) * Hx + k0 + c1g * 8];
        }

        const uint32_t aBase = sA_u + cur * bufStride;
        const uint32_t bBase = sB_u + cur * bufStride;
#pragma unroll
        for (int kk = 0; kk < 2; kk++) {
            uint32_t afr[2][4];
#pragma unroll
            for (int mt = 0; mt < 2; mt++)
                ldm_x4(aBase + (a_row + mt * 16) * (OG_PAD * 2) + kk * 32 + a_colb,
                       afr[mt]);
            uint32_t bfr[4][4];
#pragma unroll
            for (int np = 0; np < 4; np++)
                ldm_x4(bBase + (b_row + np * 16) * (OG_PAD * 2) + kk * 32 + b_colb,
                       bfr[np]);
#pragma unroll
            for (int mt = 0; mt < 2; mt++)
#pragma unroll
                for (int nt = 0; nt < 8; nt++)
                    mma_bf16(acc[mt][nt], afr[mt], &bfr[nt >> 1][(nt & 1) * 2]);
        }

        if (st < 47) {
            __syncthreads();
            *(float4*)&sA[nxt][r0g][c0g * 8] = pa0;
            *(float4*)&sA[nxt][r1g][c1g * 8] = pa1;
            *(float4*)&sB[nxt][r0g][c0g * 8] = pb0;
            *(float4*)&sB[nxt][r1g][c1g * 8] = pb1;
            __syncthreads();
        }
    }

    // ---- epilogue: acc fragment -> out[b][s][v] (+bias) ----
    const int gid = lane >> 2;            // 0..7
    const int tig = lane & 3;             // 0..3
#pragma unroll
    for (int mt = 0; mt < 2; mt++) {
        const int mrow0 = m0 + wm * 32 + mt * 16 + gid;
#pragma unroll
        for (int half = 0; half < 2; half++) {
            const int m = mrow0 + half * 8;
            const int s = m >> 8;
            const int b = m & 255;
            float* __restrict__ orow = out + ((size_t)b * Sx + s) * Vx;
#pragma unroll
            for (int nt = 0; nt < 8; nt++) {
                const int n = n0 + wn * 64 + nt * 8 + tig * 2;
                if (n + 1 < Vx) {
                    float2 v;
                    v.x = acc[mt][nt][half * 2 + 0] + bo[n];
                    v.y = acc[mt][nt][half * 2 + 1] + bo[n + 1];
                    *(float2*)&orow[n] = v;
                } else if (n < Vx) {
                    orow[n] = acc[mt][nt][half * 2 + 0] + bo[n];
                }
            }
        }
    }
}

// ---------------------------------------------------------------------------
extern "C" void kernel_launch(void* const* d_in, const int* in_sizes, int n_in,
                              void* d_out, int out_size)
{
    const float* enc   = (const float*)d_in[0];
    const int*   tok   = (const int*)  d_in[1];
    const float* emb   = (const float*)d_in[2];
    const float* W_ih  = (const float*)d_in[3];
    const float* W_hh  = (const float*)d_in[4];
    const float* b_ih  = (const float*)d_in[5];
    const float* b_hh  = (const float*)d_in[6];
    // d_in[7..9]: attn_W, attn_b, v_w -- provably unused (softmax over 1 source pos)
    const float* out_W = (const float*)d_in[10];
    const float* out_b = (const float*)d_in[11];
    float* out = (float*)d_out;

    float *p_emb_proj = nullptr, *p_const = nullptr;
    cudaGetSymbolAddress((void**)&p_emb_proj, g_emb_proj);
    cudaGetSymbolAddress((void**)&p_const, g_const);

    cudaFuncSetAttribute(lstm_step2, cudaFuncAttributeMaxDynamicSharedMemorySize,
                         SMEM_FLOATS * (int)sizeof(float));

    // 1) emb_proj[V, 4H] = embedding @ W_ih[:, :E]^T
    {
        dim3 grid(G4H / 64, (Vx + 63) / 64);
        gemm_nt64<<<grid, 256>>>(emb, Ex, W_ih, 2 * Ex, 0,
                                 nullptr, nullptr,
                                 p_emb_proj, G4H, Vx, G4H, Ex);
    }
    // 2) const[B, 4H] = enc @ W_ih[:, E:]^T + b_ih + b_hh
    {
        dim3 grid(G4H / 64, Bx / 64);
        gemm_nt64<<<grid, 256>>>(enc, Ex, W_ih, 2 * Ex, Ex,
                                 b_ih, b_hh,
                                 p_const, G4H, Bx, G4H, Ex);
    }
    // 2b) W_hh -> [unit][k][gate];  out_W -> bf16 hi/lo (padded to 1024 rows)
    transpose_whh<<<(Hx * Hx) / 256, 256>>>(W_hh);
    cvt_wo<<<(VP * Hx) / 1024, 256>>>(out_W);

    // 3) 141 sequential LSTM steps
    {
        size_t smem = SMEM_FLOATS * sizeof(float);
        for (int t = 0; t < Sx; t++)
            lstm_step2<<<128, 256, smem>>>(tok, t);
    }
    // 3b) hs -> bf16 hi/lo
    cvt_hs<<<(Mtot * Hx) / 1024, 256>>>();

    // 4) logits = hs @ out_W^T + out_b  (mma.sync bf16, 3-pass split)
    {
        dim3 grid(VP / 128, Mtot / 128);   // 8 x 282
        out_gemm_mma<<<grid, 256>>>(out_b, out);
    }
}

// round 7
// speedup vs baseline: 1.2161x; 1.0728x over previous
#include <cuda_runtime.h>
#include <cuda_bf16.h>
#include <math.h>
#include <stdint.h>

#define Bx 256
#define Sx 141
#define Vx 1000
#define VP 1024    // V padded to 8x128 tiles
#define Ex 256
#define Hx 512
#define G4H 2048   // 4*H
#define Mtot (Sx * Bx)   // 36096
#define NBLK 128   // persistent grid size (<=148 SMs -> co-resident)

// ---------------- device scratch (no runtime allocation) -------------------
__device__ float g_emb_proj[Vx * G4H];
__device__ float g_const[Bx * G4H];
__device__ float g_hs[(size_t)Sx * Bx * Hx];
__device__ float g_wt[Hx * Hx * 4];
__device__ unsigned g_bar;
__device__ __nv_bfloat16 g_hs_hi[(size_t)Mtot * Hx];
__device__ __nv_bfloat16 g_hs_lo[(size_t)Mtot * Hx];
__device__ __nv_bfloat16 g_wo_hi[(size_t)VP * Hx];
__device__ __nv_bfloat16 g_wo_lo[(size_t)VP * Hx];

// ---------------- helpers ---------------------------------------------------
__device__ __forceinline__ uint32_t smem_u32(const void* p) {
    uint32_t a;
    asm("{ .reg .u64 t; cvta.to.shared.u64 t, %1; cvt.u32.u64 %0, t; }" : "=r"(a) : "l"(p));
    return a;
}
__device__ __forceinline__ void ldm_x4(uint32_t addr, uint32_t* r) {
    asm volatile("ldmatrix.sync.aligned.m8n8.x4.shared.b16 {%0,%1,%2,%3}, [%4];"
                 : "=r"(r[0]), "=r"(r[1]), "=r"(r[2]), "=r"(r[3]) : "r"(addr));
}
__device__ __forceinline__ void mma_bf16(float* d, const uint32_t* a, const uint32_t* b) {
    asm volatile(
        "mma.sync.aligned.m16n8k16.row.col.f32.bf16.bf16.f32 "
        "{%0,%1,%2,%3}, {%4,%5,%6,%7}, {%8,%9}, {%0,%1,%2,%3};"
        : "+f"(d[0]), "+f"(d[1]), "+f"(d[2]), "+f"(d[3])
        : "r"(a[0]), "r"(a[1]), "r"(a[2]), "r"(a[3]), "r"(b[0]), "r"(b[1]));
}

// ---------------------------------------------------------------------------
// Generic NT GEMM, 64x64 tile (prep only)
// ---------------------------------------------------------------------------
__global__ __launch_bounds__(256) void gemm_nt64(
    const float* __restrict__ A, int lda,
    const float* __restrict__ W, int ldw, int koff,
    const float* __restrict__ bias0, const float* __restrict__ bias1,
    float* __restrict__ C, int ldc, int M, int N, int K)
{
    __shared__ float sA[16][64];
    __shared__ float sB[16][64];
    const int tid = threadIdx.x;
    const int tx = tid & 15;
    const int ty = tid >> 4;
    const int n0 = blockIdx.x * 64;
    const int m0 = blockIdx.y * 64;
    const int lr = tid >> 2;
    const int lk = (tid & 3) * 4;

    float acc[4][4];
#pragma unroll
    for (int i = 0; i < 4; i++)
#pragma unroll
        for (int j = 0; j < 4; j++) acc[i][j] = 0.f;

    for (int k0 = 0; k0 < K; k0 += 16) {
        int m = m0 + lr;
        float4 av = make_float4(0.f, 0.f, 0.f, 0.f);
        if (m < M) av = *(const float4*)&A[(size_t)m * lda + k0 + lk];
        sA[lk + 0][lr] = av.x; sA[lk + 1][lr] = av.y;
        sA[lk + 2][lr] = av.z; sA[lk + 3][lr] = av.w;
        int n = n0 + lr;
        float4 bv = make_float4(0.f, 0.f, 0.f, 0.f);
        if (n < N) bv = *(const float4*)&W[(size_t)n * ldw + koff + k0 + lk];
        sB[lk + 0][lr] = bv.x; sB[lk + 1][lr] = bv.y;
        sB[lk + 2][lr] = bv.z; sB[lk + 3][lr] = bv.w;
        __syncthreads();
#pragma unroll
        for (int k = 0; k < 16; k++) {
            float4 a = *(const float4*)&sA[k][ty * 4];
            float4 b = *(const float4*)&sB[k][tx * 4];
            float aa[4] = {a.x, a.y, a.z, a.w};
            float bb[4] = {b.x, b.y, b.z, b.w};
#pragma unroll
            for (int i = 0; i < 4; i++)
#pragma unroll
                for (int j = 0; j < 4; j++)
                    acc[i][j] = fmaf(aa[i], bb[j], acc[i][j]);
        }
        __syncthreads();
    }
#pragma unroll
    for (int i = 0; i < 4; i++) {
        int m = m0 + ty * 4 + i;
        if (m >= M) continue;
#pragma unroll
        for (int j = 0; j < 4; j++) {
            int n = n0 + tx * 4 + j;
            if (n >= N) continue;
            float v = acc[i][j];
            if (bias0) v += bias0[n];
            if (bias1) v += bias1[n];
            C[(size_t)m * ldc + n] = v;
        }
    }
}

// ---------------------------------------------------------------------------
__global__ __launch_bounds__(256) void transpose_whh(const float* __restrict__ W)
{
    int i = blockIdx.x * 256 + threadIdx.x;
    int u = i >> 9;
    int k = i & 511;
    float4 v;
    v.x = W[(size_t)(0 * Hx + u) * Hx + k];
    v.y = W[(size_t)(1 * Hx + u) * Hx + k];
    v.z = W[(size_t)(2 * Hx + u) * Hx + k];
    v.w = W[(size_t)(3 * Hx + u) * Hx + k];
    *(float4*)&g_wt[(size_t)i * 4] = v;
}

__global__ void zero_bar() { g_bar = 0u; }

// ---------------------------------------------------------------------------
// Persistent LSTM: one kernel runs all 141 steps with a software grid barrier.
// 128 blocks x 256 threads; block owns 4 units x all 4 gates x 256 batches.
// W slice staged in smem ONCE; c lives in registers; h chained via g_hs rows
// with L1-bypass (ldcg/stcg) + threadfence around the barrier.
// ---------------------------------------------------------------------------
#define SWU 2052
#define HROW 260
#define HBUF (16 * HROW)
#define SMEM_FLOATS (4 * SWU + 2 * HBUF)

__global__ __launch_bounds__(256) void lstm_persist(const int* __restrict__ tok)
{
    extern __shared__ float smem[];
    float* sw = smem;
    float* hb = smem + 4 * SWU;

    const int tid = threadIdx.x;
    const int uu = tid & 3;
    const int bg = tid >> 2;
    const int u0 = blockIdx.x * 4;
    const int u  = u0 + uu;
    const int lb = tid >> 2;
    const int lj = tid & 3;

    // ---- stage W slice once: 2048 float4 ----
    {
        const float4* src = (const float4*)&g_wt[(size_t)u0 * Hx * 4];
#pragma unroll
        for (int r = 0; r < 8; r++) {
            int i = r * 256 + tid;
            int cu = i >> 9;
            int rem = i & 511;
            float4 v = src[i];
            *(float4*)&sw[cu * SWU + rem * 4] = v;
        }
    }
    __syncthreads();

    const float* wbase = sw + uu * SWU;
    float creg[4] = {0.f, 0.f, 0.f, 0.f};

    for (int t = 0; t < Sx; t++) {
        float acc[4][4];
#pragma unroll
        for (int i = 0; i < 4; i++)
#pragma unroll
            for (int g = 0; g < 4; g++) acc[i][g] = 0.f;

        if (t > 0) {
            const float* __restrict__ hin = g_hs + (size_t)(t - 1) * Bx * Hx;

            float4 pf[4];
#pragma unroll
            for (int it = 0; it < 4; it++)
                pf[it] = __ldcg((const float4*)&hin[(size_t)(it * 64 + lb) * Hx + lj * 4]);
            {
                float* hb0 = hb;
#pragma unroll
                for (int it = 0; it < 4; it++) {
                    int b = it * 64 + lb;
                    hb0[(lj * 4 + 0) * HROW + b] = pf[it].x;
                    hb0[(lj * 4 + 1) * HROW + b] = pf[it].y;
                    hb0[(lj * 4 + 2) * HROW + b] = pf[it].z;
                    hb0[(lj * 4 + 3) * HROW + b] = pf[it].w;
                }
            }
            __syncthreads();

            for (int kt = 0; kt < 32; kt++) {
                const float* cur = hb + (kt & 1) * HBUF;
                float* nxt = hb + ((kt + 1) & 1) * HBUF;
                if (kt < 31) {
                    int k0 = (kt + 1) * 16;
#pragma unroll
                    for (int it = 0; it < 4; it++)
                        pf[it] = __ldcg((const float4*)&hin[(size_t)(it * 64 + lb) * Hx + k0 + lj * 4]);
                }
                const float* hbase = cur + bg * 4;
                const float* wk = wbase + kt * 16 * 4;
#pragma unroll
                for (int k = 0; k < 16; k++) {
                    float4 wv = *(const float4*)&wk[k * 4];
                    float4 hv = *(const float4*)&hbase[k * HROW];
                    acc[0][0] = fmaf(hv.x, wv.x, acc[0][0]);
                    acc[0][1] = fmaf(hv.x, wv.y, acc[0][1]);
                    acc[0][2] = fmaf(hv.x, wv.z, acc[0][2]);
                    acc[0][3] = fmaf(hv.x, wv.w, acc[0][3]);
                    acc[1][0] = fmaf(hv.y, wv.x, acc[1][0]);
                    acc[1][1] = fmaf(hv.y, wv.y, acc[1][1]);
                    acc[1][2] = fmaf(hv.y, wv.z, acc[1][2]);
                    acc[1][3] = fmaf(hv.y, wv.w, acc[1][3]);
                    acc[2][0] = fmaf(hv.z, wv.x, acc[2][0]);
                    acc[2][1] = fmaf(hv.z, wv.y, acc[2][1]);
                    acc[2][2] = fmaf(hv.z, wv.z, acc[2][2]);
                    acc[2][3] = fmaf(hv.z, wv.w, acc[2][3]);
                    acc[3][0] = fmaf(hv.w, wv.x, acc[3][0]);
                    acc[3][1] = fmaf(hv.w, wv.y, acc[3][1]);
                    acc[3][2] = fmaf(hv.w, wv.z, acc[3][2]);
                    acc[3][3] = fmaf(hv.w, wv.w, acc[3][3]);
                }
                if (kt < 31) {
                    __syncthreads();
#pragma unroll
                    for (int it = 0; it < 4; it++) {
                        int b = it * 64 + lb;
                        nxt[(lj * 4 + 0) * HROW + b] = pf[it].x;
                        nxt[(lj * 4 + 1) * HROW + b] = pf[it].y;
                        nxt[(lj * 4 + 2) * HROW + b] = pf[it].z;
                        nxt[(lj * 4 + 3) * HROW + b] = pf[it].w;
                    }
                    __syncthreads();
                }
            }
        }

        // ---- pointwise LSTM epilogue ----
        float* __restrict__ hout = g_hs + (size_t)t * Bx * Hx;
#pragma unroll
        for (int i = 0; i < 4; i++) {
            const int b = bg * 4 + i;
            const int tk = __ldg(&tok[b * Sx + t]);
            const float* __restrict__ ep = g_emb_proj + (size_t)tk * G4H;
            const float* __restrict__ cs = g_const + (size_t)b * G4H;

            float gi = acc[i][0] + ep[0 * Hx + u] + cs[0 * Hx + u];
            float gf = acc[i][1] + ep[1 * Hx + u] + cs[1 * Hx + u];
            float gg = acc[i][2] + ep[2 * Hx + u] + cs[2 * Hx + u];
            float go = acc[i][3] + ep[3 * Hx + u] + cs[3 * Hx + u];

            float is = 1.f / (1.f + expf(-gi));
            float fs = 1.f / (1.f + expf(-gf));
            float gt = tanhf(gg);
            float os = 1.f / (1.f + expf(-go));

            float cn = fs * creg[i] + is * gt;
            float hn = os * tanhf(cn);
            creg[i] = cn;
            __stcg(&hout[(size_t)b * Hx + u], hn);
        }

        // ---- grid barrier (skip after last step) ----
        if (t < Sx - 1) {
            __syncthreads();
            if (tid == 0) {
                __threadfence();
                atomicAdd(&g_bar, 1u);
                const unsigned target = (unsigned)NBLK * (unsigned)(t + 1);
                while (*(volatile unsigned*)&g_bar < target) {}
                __threadfence();
            }
            __syncthreads();
        }
    }
}

// ---------------------------------------------------------------------------
// fp32 -> bf16 hi/lo split conversions
// ---------------------------------------------------------------------------
__global__ __launch_bounds__(256) void cvt_hs()
{
    size_t i = ((size_t)blockIdx.x * 256 + threadIdx.x) * 4;
    float4 v = *(const float4*)&g_hs[i];
    float x[4] = {v.x, v.y, v.z, v.w};
    __nv_bfloat16 hi[4], lo[4];
#pragma unroll
    for (int j = 0; j < 4; j++) {
        hi[j] = __float2bfloat16(x[j]);
        lo[j] = __float2bfloat16(x[j] - __bfloat162float(hi[j]));
    }
    *(uint2*)&g_hs_hi[i] = *(uint2*)hi;
    *(uint2*)&g_hs_lo[i] = *(uint2*)lo;
}

__global__ __launch_bounds__(256) void cvt_wo(const float* __restrict__ Wo)
{
    size_t i = ((size_t)blockIdx.x * 256 + threadIdx.x) * 4;
    int row = (int)(i >> 9);
    float x[4] = {0.f, 0.f, 0.f, 0.f};
    if (row < Vx) {
        float4 v = *(const float4*)&Wo[i];
        x[0] = v.x; x[1] = v.y; x[2] = v.z; x[3] = v.w;
    }
    __nv_bfloat16 hi[4], lo[4];
#pragma unroll
    for (int j = 0; j < 4; j++) {
        hi[j] = __float2bfloat16(x[j]);
        lo[j] = __float2bfloat16(x[j] - __bfloat162float(hi[j]));
    }
    *(uint2*)&g_wo_hi[i] = *(uint2*)hi;
    *(uint2*)&g_wo_lo[i] = *(uint2*)lo;
}

// ---------------------------------------------------------------------------
// Output GEMM with mma.sync bf16 (3-pass hi/lo split). (unchanged from R6)
// ---------------------------------------------------------------------------
#define OG_PAD 40

__global__ __launch_bounds__(256) void out_gemm_mma(
    const float* __restrict__ bo, float* __restrict__ out)
{
    __shared__ __align__(16) __nv_bfloat16 sA[2][128][OG_PAD];
    __shared__ __align__(16) __nv_bfloat16 sB[2][128][OG_PAD];

    const int tid = threadIdx.x;
    const int wid = tid >> 5;
    const int lane = tid & 31;
    const int wm = wid & 3;
    const int wn = wid >> 2;
    const int n0 = blockIdx.x * 128;
    const int m0 = blockIdx.y * 128;

    const uint32_t sA_u = smem_u32(sA);
    const uint32_t sB_u = smem_u32(sB);
    const uint32_t bufStride = 128 * OG_PAD * 2;

    float acc[2][8][4];
#pragma unroll
    for (int mt = 0; mt < 2; mt++)
#pragma unroll
        for (int nt = 0; nt < 8; nt++)
#pragma unroll
            for (int e = 0; e < 4; e++) acc[mt][nt][e] = 0.f;

    const uint32_t a_row = wm * 32 + (lane & 15);
    const uint32_t a_colb = (lane >> 4) * 16;
    const uint32_t b_row = wn * 64 + ((lane >> 3) >= 2 ? 8 : 0) + (lane & 7);
    const uint32_t b_colb = ((lane >> 3) & 1) * 16;

    const int s0 = tid;
    const int r0g = s0 >> 2, c0g = s0 & 3;
    const int s1 = tid + 256;
    const int r1g = s1 >> 2, c1g = s1 & 3;

    float4 pa0, pa1, pb0, pb1;
    pa0 = *(const float4*)&g_hs_hi[(size_t)(m0 + r0g) * Hx + c0g * 8];
    pa1 = *(const float4*)&g_hs_hi[(size_t)(m0 + r1g) * Hx + c1g * 8];
    pb0 = *(const float4*)&g_wo_hi[(size_t)(n0 + r0g) * Hx + c0g * 8];
    pb1 = *(const float4*)&g_wo_hi[(size_t)(n0 + r1g) * Hx + c1g * 8];
    *(float4*)&sA[0][r0g][c0g * 8] = pa0;
    *(float4*)&sA[0][r1g][c1g * 8] = pa1;
    *(float4*)&sB[0][r0g][c0g * 8] = pb0;
    *(float4*)&sB[0][r1g][c1g * 8] = pb1;
    __syncthreads();

    for (int st = 0; st < 48; st++) {
        const int cur = st & 1;
        const int nxt = cur ^ 1;
        if (st < 47) {
            const int p = (st + 1) >> 4;
            const int k0 = ((st + 1) & 15) * 32;
            const __nv_bfloat16* __restrict__ Asrc = (p == 1) ? g_hs_lo : g_hs_hi;
            const __nv_bfloat16* __restrict__ Bsrc = (p == 2) ? g_wo_lo : g_wo_hi;
            pa0 = *(const float4*)&Asrc[(size_t)(m0 + r0g) * Hx + k0 + c0g * 8];
            pa1 = *(const float4*)&Asrc[(size_t)(m0 + r1g) * Hx + k0 + c1g * 8];
            pb0 = *(const float4*)&Bsrc[(size_t)(n0 + r0g) * Hx + k0 + c0g * 8];
            pb1 = *(const float4*)&Bsrc[(size_t)(n0 + r1g) * Hx + k0 + c1g * 8];
        }

        const uint32_t aBase = sA_u + cur * bufStride;
        const uint32_t bBase = sB_u + cur * bufStride;
#pragma unroll
        for (int kk = 0; kk < 2; kk++) {
            uint32_t afr[2][4];
#pragma unroll
            for (int mt = 0; mt < 2; mt++)
                ldm_x4(aBase + (a_row + mt * 16) * (OG_PAD * 2) + kk * 32 + a_colb,
                       afr[mt]);
            uint32_t bfr[4][4];
#pragma unroll
            for (int np = 0; np < 4; np++)
                ldm_x4(bBase + (b_row + np * 16) * (OG_PAD * 2) + kk * 32 + b_colb,
                       bfr[np]);
#pragma unroll
            for (int mt = 0; mt < 2; mt++)
#pragma unroll
                for (int nt = 0; nt < 8; nt++)
                    mma_bf16(acc[mt][nt], afr[mt], &bfr[nt >> 1][(nt & 1) * 2]);
        }

        if (st < 47) {
            __syncthreads();
            *(float4*)&sA[nxt][r0g][c0g * 8] = pa0;
            *(float4*)&sA[nxt][r1g][c1g * 8] = pa1;
            *(float4*)&sB[nxt][r0g][c0g * 8] = pb0;
            *(float4*)&sB[nxt][r1g][c1g * 8] = pb1;
            __syncthreads();
        }
    }

    const int gid = lane >> 2;
    const int tig = lane & 3;
#pragma unroll
    for (int mt = 0; mt < 2; mt++) {
        const int mrow0 = m0 + wm * 32 + mt * 16 + gid;
#pragma unroll
        for (int half = 0; half < 2; half++) {
            const int m = mrow0 + half * 8;
            const int s = m >> 8;
            const int b = m & 255;
            float* __restrict__ orow = out + ((size_t)b * Sx + s) * Vx;
#pragma unroll
            for (int nt = 0; nt < 8; nt++) {
                const int n = n0 + wn * 64 + nt * 8 + tig * 2;
                if (n + 1 < Vx) {
                    float2 v;
                    v.x = acc[mt][nt][half * 2 + 0] + bo[n];
                    v.y = acc[mt][nt][half * 2 + 1] + bo[n + 1];
                    *(float2*)&orow[n] = v;
                } else if (n < Vx) {
                    orow[n] = acc[mt][nt][half * 2 + 0] + bo[n];
                }
            }
        }
    }
}

// ---------------------------------------------------------------------------
extern "C" void kernel_launch(void* const* d_in, const int* in_sizes, int n_in,
                              void* d_out, int out_size)
{
    const float* enc   = (const float*)d_in[0];
    const int*   tok   = (const int*)  d_in[1];
    const float* emb   = (const float*)d_in[2];
    const float* W_ih  = (const float*)d_in[3];
    const float* W_hh  = (const float*)d_in[4];
    const float* b_ih  = (const float*)d_in[5];
    const float* b_hh  = (const float*)d_in[6];
    // d_in[7..9]: attn_W, attn_b, v_w -- provably unused (softmax over 1 source pos)
    const float* out_W = (const float*)d_in[10];
    const float* out_b = (const float*)d_in[11];
    float* out = (float*)d_out;

    float *p_emb_proj = nullptr, *p_const = nullptr;
    cudaGetSymbolAddress((void**)&p_emb_proj, g_emb_proj);
    cudaGetSymbolAddress((void**)&p_const, g_const);

    cudaFuncSetAttribute(lstm_persist, cudaFuncAttributeMaxDynamicSharedMemorySize,
                         SMEM_FLOATS * (int)sizeof(float));

    // 1) emb_proj[V, 4H] = embedding @ W_ih[:, :E]^T
    {
        dim3 grid(G4H / 64, (Vx + 63) / 64);
        gemm_nt64<<<grid, 256>>>(emb, Ex, W_ih, 2 * Ex, 0,
                                 nullptr, nullptr,
                                 p_emb_proj, G4H, Vx, G4H, Ex);
    }
    // 2) const[B, 4H] = enc @ W_ih[:, E:]^T + b_ih + b_hh
    {
        dim3 grid(G4H / 64, Bx / 64);
        gemm_nt64<<<grid, 256>>>(enc, Ex, W_ih, 2 * Ex, Ex,
                                 b_ih, b_hh,
                                 p_const, G4H, Bx, G4H, Ex);
    }
    // 2b) W_hh -> [unit][k][gate];  out_W -> bf16 hi/lo;  reset grid barrier
    transpose_whh<<<(Hx * Hx) / 256, 256>>>(W_hh);
    cvt_wo<<<(VP * Hx) / 1024, 256>>>(out_W);
    zero_bar<<<1, 1>>>();

    // 3) ALL 141 LSTM steps in one persistent kernel (software grid barrier)
    lstm_persist<<<NBLK, 256, SMEM_FLOATS * sizeof(float)>>>(tok);

    // 3b) hs -> bf16 hi/lo
    cvt_hs<<<(Mtot * Hx) / 1024, 256>>>();

    // 4) logits = hs @ out_W^T + out_b  (mma.sync bf16, 3-pass split)
    {
        dim3 grid(VP / 128, Mtot / 128);   // 8 x 282
        out_gemm_mma<<<grid, 256>>>(out_b, out);
    }
}

// round 9
// speedup vs baseline: 2.0050x; 1.6487x over previous
#include <cuda_runtime.h>
#include <cuda_bf16.h>
#include <math.h>
#include <stdint.h>

#define Bx 256
#define Sx 141
#define Vx 1000
#define VP 1024
#define Ex 256
#define Hx 512
#define G4H 2048
#define Mtot (Sx * Bx)   // 36096
#define NBLK 128

// ---------------- device scratch (no runtime allocation) -------------------
__device__ float g_emb_proj[Vx * G4H];            // [gate*512+u] layout
__device__ float g_const[Bx * G4H];
__device__ unsigned g_bar;
__device__ __nv_bfloat16 g_hs_hi[(size_t)Mtot * Hx];
__device__ __nv_bfloat16 g_hs_lo[(size_t)Mtot * Hx];
__device__ __nv_bfloat16 g_wo_hi[(size_t)VP * Hx];
__device__ __nv_bfloat16 g_wo_lo[(size_t)VP * Hx];
__device__ __nv_bfloat16 g_whh_hi[G4H * Hx];      // [c=u*4+g][k]
__device__ __nv_bfloat16 g_whh_lo[G4H * Hx];

// ---------------- helpers ---------------------------------------------------
__device__ __forceinline__ uint32_t smem_u32(const void* p) {
    uint32_t a;
    asm("{ .reg .u64 t; cvta.to.shared.u64 t, %1; cvt.u32.u64 %0, t; }" : "=r"(a) : "l"(p));
    return a;
}
__device__ __forceinline__ void ldm_x4(uint32_t addr, uint32_t* r) {
    asm volatile("ldmatrix.sync.aligned.m8n8.x4.shared.b16 {%0,%1,%2,%3}, [%4];"
                 : "=r"(r[0]), "=r"(r[1]), "=r"(r[2]), "=r"(r[3]) : "r"(addr));
}
__device__ __forceinline__ void mma_bf16(float* d, const uint32_t* a, const uint32_t* b) {
    asm volatile(
        "mma.sync.aligned.m16n8k16.row.col.f32.bf16.bf16.f32 "
        "{%0,%1,%2,%3}, {%4,%5,%6,%7}, {%8,%9}, {%0,%1,%2,%3};"
        : "+f"(d[0]), "+f"(d[1]), "+f"(d[2]), "+f"(d[3])
        : "r"(a[0]), "r"(a[1]), "r"(a[2]), "r"(a[3]), "r"(b[0]), "r"(b[1]));
}

// ---------------------------------------------------------------------------
// Generic NT GEMM, 64x64 tile (prep only)
// ---------------------------------------------------------------------------
__global__ __launch_bounds__(256) void gemm_nt64(
    const float* __restrict__ A, int lda,
    const float* __restrict__ W, int ldw, int koff,
    const float* __restrict__ bias0, const float* __restrict__ bias1,
    float* __restrict__ C, int ldc, int M, int N, int K)
{
    __shared__ float sA[16][64];
    __shared__ float sB[16][64];
    const int tid = threadIdx.x;
    const int tx = tid & 15;
    const int ty = tid >> 4;
    const int n0 = blockIdx.x * 64;
    const int m0 = blockIdx.y * 64;
    const int lr = tid >> 2;
    const int lk = (tid & 3) * 4;

    float acc[4][4];
#pragma unroll
    for (int i = 0; i < 4; i++)
#pragma unroll
        for (int j = 0; j < 4; j++) acc[i][j] = 0.f;

    for (int k0 = 0; k0 < K; k0 += 16) {
        int m = m0 + lr;
        float4 av = make_float4(0.f, 0.f, 0.f, 0.f);
        if (m < M) av = *(const float4*)&A[(size_t)m * lda + k0 + lk];
        sA[lk + 0][lr] = av.x; sA[lk + 1][lr] = av.y;
        sA[lk + 2][lr] = av.z; sA[lk + 3][lr] = av.w;
        int n = n0 + lr;
        float4 bv = make_float4(0.f, 0.f, 0.f, 0.f);
        if (n < N) bv = *(const float4*)&W[(size_t)n * ldw + koff + k0 + lk];
        sB[lk + 0][lr] = bv.x; sB[lk + 1][lr] = bv.y;
        sB[lk + 2][lr] = bv.z; sB[lk + 3][lr] = bv.w;
        __syncthreads();
#pragma unroll
        for (int k = 0; k < 16; k++) {
            float4 a = *(const float4*)&sA[k][ty * 4];
            float4 b = *(const float4*)&sB[k][tx * 4];
            float aa[4] = {a.x, a.y, a.z, a.w};
            float bb[4] = {b.x, b.y, b.z, b.w};
#pragma unroll
            for (int i = 0; i < 4; i++)
#pragma unroll
                for (int j = 0; j < 4; j++)
                    acc[i][j] = fmaf(aa[i], bb[j], acc[i][j]);
        }
        __syncthreads();
    }
#pragma unroll
    for (int i = 0; i < 4; i++) {
        int m = m0 + ty * 4 + i;
        if (m >= M) continue;
#pragma unroll
        for (int j = 0; j < 4; j++) {
            int n = n0 + tx * 4 + j;
            if (n >= N) continue;
            float v = acc[i][j];
            if (bias0) v += bias0[n];
            if (bias1) v += bias1[n];
            C[(size_t)m * ldc + n] = v;
        }
    }
}

// ---------------------------------------------------------------------------
// W_hh [4H, H] -> bf16 hi/lo in layout [c = u*4+g][k]
// ---------------------------------------------------------------------------
__global__ __launch_bounds__(256) void cvt_whh(const float* __restrict__ W)
{
    int i = blockIdx.x * 256 + threadIdx.x;   // 2048 cols x 32 k-segments(16)
    int c = i >> 5;
    int ks = (i & 31) * 16;
    int u = c >> 2;
    int g = c & 3;
    const float* src = &W[(size_t)(g * Hx + u) * Hx + ks];
    __nv_bfloat16 hi[16], lo[16];
#pragma unroll
    for (int j = 0; j < 16; j++) {
        float x = src[j];
        hi[j] = __float2bfloat16(x);
        lo[j] = __float2bfloat16(x - __bfloat162float(hi[j]));
    }
    *(uint4*)&g_whh_hi[(size_t)c * Hx + ks] = *(uint4*)&hi[0];
    *(uint4*)&g_whh_hi[(size_t)c * Hx + ks + 8] = *(uint4*)&hi[8];
    *(uint4*)&g_whh_lo[(size_t)c * Hx + ks] = *(uint4*)&lo[0];
    *(uint4*)&g_whh_lo[(size_t)c * Hx + ks + 8] = *(uint4*)&lo[8];
}

__global__ __launch_bounds__(256) void cvt_wo(const float* __restrict__ Wo)
{
    size_t i = ((size_t)blockIdx.x * 256 + threadIdx.x) * 4;
    int row = (int)(i >> 9);
    float x[4] = {0.f, 0.f, 0.f, 0.f};
    if (row < Vx) {
        float4 v = *(const float4*)&Wo[i];
        x[0] = v.x; x[1] = v.y; x[2] = v.z; x[3] = v.w;
    }
    __nv_bfloat16 hi[4], lo[4];
#pragma unroll
    for (int j = 0; j < 4; j++) {
        hi[j] = __float2bfloat16(x[j]);
        lo[j] = __float2bfloat16(x[j] - __bfloat162float(hi[j]));
    }
    *(uint2*)&g_wo_hi[i] = *(uint2*)hi;
    *(uint2*)&g_wo_lo[i] = *(uint2*)lo;
}

__global__ void zero_bar() { g_bar = 0u; }

// ---------------------------------------------------------------------------
// Persistent tensor-core LSTM.
// 128 blocks x 256 thr. Block = 128 batches x 32 gate-cols (8 units x 4 gates).
// grid: bx&63 -> col tile (n0 = 32*that, u0 = 8*that), bx>>6 -> batch half.
// W slice (hi+lo, 32x512) staged in smem once. h read as bf16 hi/lo; GEMM =
// 3-combo mma (Ahi*Whi + Alo*Whi + Ahi*Wlo) into fp32 acc. c in registers.
// ---------------------------------------------------------------------------
#define WROW 520                         // bf16 per W smem row (pad)
#define SW_BYTES (2 * 32 * WROW * 2)     // 66560
#define AROW 40                          // bf16 per A smem row (pad)
#define SA_BYTES (2 * 2 * 128 * AROW * 2) // 40960
#define SG_OFF (SW_BYTES + SA_BYTES)
#define SGROW 33
#define LP_SMEM (SG_OFF + 128 * SGROW * 4) // 124416

__global__ __launch_bounds__(256) void lstm_persist(const int* __restrict__ tok)
{
    extern __shared__ char sm[];
    __nv_bfloat16* sw = (__nv_bfloat16*)sm;
    float* sg = (float*)(sm + SG_OFF);
    const uint32_t sw_u = smem_u32(sm);
    const uint32_t sa_u = sw_u + SW_BYTES;

    const int tid = threadIdx.x;
    const int wid = tid >> 5;
    const int lane = tid & 31;
    const int wm = wid & 3;               // 4 m-warps (32 rows each)
    const int wn = wid >> 2;              // 2 n-warps (16 cols each)
    const int nIdx = blockIdx.x & 63;
    const int m0 = (blockIdx.x >> 6) * 128;
    const int n0 = nIdx * 32;             // gate-col base
    const int u0 = nIdx * 8;              // unit base

    // ---- stage W slice (hi+lo) once: rows n0..n0+31, all 512 k ----
    // FIX vs R8: 8 bf16 = 16 bytes -> uint4 copy (uint2 left odd halves garbage -> NaN)
#pragma unroll
    for (int var = 0; var < 2; var++) {
        const __nv_bfloat16* src = var ? g_whh_lo : g_whh_hi;
#pragma unroll
        for (int it = 0; it < 8; it++) {
            int s = it * 256 + tid;        // 2048 segs: 32 rows x 64 segs
            int r = s >> 6;
            int cs = s & 63;
            *(uint4*)&sw[(var * 32 + r) * WROW + cs * 8] =
                *(const uint4*)&src[(size_t)(n0 + r) * Hx + cs * 8];
        }
    }
    __syncthreads();

    // ldmatrix lane addressing
    const uint32_t a_row = wm * 32 + (lane & 15);
    const uint32_t a_colb = (lane >> 4) * 16;
    const uint32_t b_row = wn * 16 + ((lane >> 3) >= 2 ? 8 : 0) + (lane & 7);
    const uint32_t b_colb = ((lane >> 3) & 1) * 16;

    const int eb = tid & 127;             // epilogue batch-local
    const int uh = tid >> 7;              // epilogue unit half

    float creg[4] = {0.f, 0.f, 0.f, 0.f};

    for (int t = 0; t < Sx; t++) {
        float acc[2][2][4];
#pragma unroll
        for (int mt = 0; mt < 2; mt++)
#pragma unroll
            for (int nt = 0; nt < 2; nt++)
#pragma unroll
                for (int e = 0; e < 4; e++) acc[mt][nt][e] = 0.f;

        if (t > 0) {
            const size_t hbase = ((size_t)(t - 1) * Bx + m0) * Hx;
            float4 p[2][2];
            // preload chunk 0
#pragma unroll
            for (int var = 0; var < 2; var++) {
                const __nv_bfloat16* src = var ? g_hs_lo : g_hs_hi;
#pragma unroll
                for (int it = 0; it < 2; it++) {
                    int s = it * 256 + tid;
                    int r = s >> 2, cs = s & 3;
                    p[var][it] = __ldcg((const float4*)&src[hbase + (size_t)r * Hx + cs * 8]);
                }
            }
#pragma unroll
            for (int var = 0; var < 2; var++)
#pragma unroll
                for (int it = 0; it < 2; it++) {
                    int s = it * 256 + tid;
                    int r = s >> 2, cs = s & 3;
                    *(float4*)(sm + SW_BYTES + ((0 * 2 + var) * 128 + r) * (AROW * 2) + cs * 16) = p[var][it];
                }
            __syncthreads();

            for (int ct = 0; ct < 16; ct++) {
                const int buf = ct & 1;
                if (ct < 15) {
                    const int k0 = (ct + 1) * 32;
#pragma unroll
                    for (int var = 0; var < 2; var++) {
                        const __nv_bfloat16* src = var ? g_hs_lo : g_hs_hi;
#pragma unroll
                        for (int it = 0; it < 2; it++) {
                            int s = it * 256 + tid;
                            int r = s >> 2, cs = s & 3;
                            p[var][it] = __ldcg((const float4*)&src[hbase + (size_t)r * Hx + k0 + cs * 8]);
                        }
                    }
                }
                // compute chunk ct (k local 0..31)
                const uint32_t aHiBase = sa_u + (buf * 2 + 0) * 128 * (AROW * 2);
                const uint32_t aLoBase = sa_u + (buf * 2 + 1) * 128 * (AROW * 2);
                const uint32_t kByte = (uint32_t)ct * 64;   // 32 k * 2B
#pragma unroll
                for (int kk = 0; kk < 2; kk++) {
                    uint32_t ahi[2][4], alo[2][4], whiF[4], wloF[4];
#pragma unroll
                    for (int mt = 0; mt < 2; mt++) {
                        ldm_x4(aHiBase + (a_row + mt * 16) * (AROW * 2) + kk * 32 + a_colb, ahi[mt]);
                        ldm_x4(aLoBase + (a_row + mt * 16) * (AROW * 2) + kk * 32 + a_colb, alo[mt]);
                    }
                    const uint32_t wcol = kByte + kk * 32 + b_colb;
                    ldm_x4(sw_u + (0 * 32 + b_row) * (WROW * 2) + wcol, whiF);
                    ldm_x4(sw_u + (1 * 32 + b_row) * (WROW * 2) + wcol, wloF);
#pragma unroll
                    for (int mt = 0; mt < 2; mt++)
#pragma unroll
                        for (int nt = 0; nt < 2; nt++) {
                            mma_bf16(acc[mt][nt], ahi[mt], &whiF[nt * 2]);
                            mma_bf16(acc[mt][nt], alo[mt], &whiF[nt * 2]);
                            mma_bf16(acc[mt][nt], ahi[mt], &wloF[nt * 2]);
                        }
                }
                if (ct < 15) {
                    __syncthreads();
                    const int nb = buf ^ 1;
#pragma unroll
                    for (int var = 0; var < 2; var++)
#pragma unroll
                        for (int it = 0; it < 2; it++) {
                            int s = it * 256 + tid;
                            int r = s >> 2, cs = s & 3;
                            *(float4*)(sm + SW_BYTES + ((nb * 2 + var) * 128 + r) * (AROW * 2) + cs * 16) = p[var][it];
                        }
                    __syncthreads();
                }
            }

            // ---- fragments -> smem gates ----
            const int gid = lane >> 2;
            const int tig = lane & 3;
#pragma unroll
            for (int mt = 0; mt < 2; mt++)
#pragma unroll
                for (int nt = 0; nt < 2; nt++) {
                    int mr = wm * 32 + mt * 16 + gid;
                    int cc = wn * 16 + nt * 8 + tig * 2;
                    sg[mr * SGROW + cc] = acc[mt][nt][0];
                    sg[mr * SGROW + cc + 1] = acc[mt][nt][1];
                    sg[(mr + 8) * SGROW + cc] = acc[mt][nt][2];
                    sg[(mr + 8) * SGROW + cc + 1] = acc[mt][nt][3];
                }
            __syncthreads();
        }

        // ---- per-thread LSTM epilogue: b = m0+eb, units u0 + uh*4 + j ----
        {
            const int b = m0 + eb;
            const int tkn = __ldg(&tok[b * Sx + t]);
            const float* __restrict__ ep = g_emb_proj + (size_t)tkn * G4H;
            const float* __restrict__ cs = g_const + (size_t)b * G4H;
            __nv_bfloat16 hi4[4], lo4[4];
#pragma unroll
            for (int j = 0; j < 4; j++) {
                const int ul = uh * 4 + j;
                const int u = u0 + ul;
                float gi = ep[0 * Hx + u] + cs[0 * Hx + u];
                float gf = ep[1 * Hx + u] + cs[1 * Hx + u];
                float gg = ep[2 * Hx + u] + cs[2 * Hx + u];
                float go = ep[3 * Hx + u] + cs[3 * Hx + u];
                if (t > 0) {
                    gi += sg[eb * SGROW + ul * 4 + 0];
                    gf += sg[eb * SGROW + ul * 4 + 1];
                    gg += sg[eb * SGROW + ul * 4 + 2];
                    go += sg[eb * SGROW + ul * 4 + 3];
                }
                float is = 1.f / (1.f + expf(-gi));
                float fs = 1.f / (1.f + expf(-gf));
                float gt = tanhf(gg);
                float os = 1.f / (1.f + expf(-go));
                float cn = fs * creg[j] + is * gt;
                float hn = os * tanhf(cn);
                creg[j] = cn;
                hi4[j] = __float2bfloat16(hn);
                lo4[j] = __float2bfloat16(hn - __bfloat162float(hi4[j]));
            }
            const size_t hoff = ((size_t)t * Bx + b) * Hx + u0 + uh * 4;
            __stcg((uint2*)&g_hs_hi[hoff], *(uint2*)hi4);
            __stcg((uint2*)&g_hs_lo[hoff], *(uint2*)lo4);
        }

        // ---- grid barrier ----
        if (t < Sx - 1) {
            __syncthreads();
            if (tid == 0) {
                __threadfence();
                atomicAdd(&g_bar, 1u);
                const unsigned target = (unsigned)NBLK * (unsigned)(t + 1);
                while (*(volatile unsigned*)&g_bar < target) {}
                __threadfence();
            }
            __syncthreads();
        }
    }
}

// ---------------------------------------------------------------------------
// Output GEMM with mma.sync bf16 (3-pass hi/lo split). (unchanged)
// ---------------------------------------------------------------------------
#define OG_PAD 40

__global__ __launch_bounds__(256) void out_gemm_mma(
    const float* __restrict__ bo, float* __restrict__ out)
{
    __shared__ __align__(16) __nv_bfloat16 sA[2][128][OG_PAD];
    __shared__ __align__(16) __nv_bfloat16 sB[2][128][OG_PAD];

    const int tid = threadIdx.x;
    const int wid = tid >> 5;
    const int lane = tid & 31;
    const int wm = wid & 3;
    const int wn = wid >> 2;
    const int n0 = blockIdx.x * 128;
    const int m0 = blockIdx.y * 128;

    const uint32_t sA_u = smem_u32(sA);
    const uint32_t sB_u = smem_u32(sB);
    const uint32_t bufStride = 128 * OG_PAD * 2;

    float acc[2][8][4];
#pragma unroll
    for (int mt = 0; mt < 2; mt++)
#pragma unroll
        for (int nt = 0; nt < 8; nt++)
#pragma unroll
            for (int e = 0; e < 4; e++) acc[mt][nt][e] = 0.f;

    const uint32_t a_row = wm * 32 + (lane & 15);
    const uint32_t a_colb = (lane >> 4) * 16;
    const uint32_t b_row = wn * 64 + ((lane >> 3) >= 2 ? 8 : 0) + (lane & 7);
    const uint32_t b_colb = ((lane >> 3) & 1) * 16;

    const int s0 = tid;
    const int r0g = s0 >> 2, c0g = s0 & 3;
    const int s1 = tid + 256;
    const int r1g = s1 >> 2, c1g = s1 & 3;

    float4 pa0, pa1, pb0, pb1;
    pa0 = *(const float4*)&g_hs_hi[(size_t)(m0 + r0g) * Hx + c0g * 8];
    pa1 = *(const float4*)&g_hs_hi[(size_t)(m0 + r1g) * Hx + c1g * 8];
    pb0 = *(const float4*)&g_wo_hi[(size_t)(n0 + r0g) * Hx + c0g * 8];
    pb1 = *(const float4*)&g_wo_hi[(size_t)(n0 + r1g) * Hx + c1g * 8];
    *(float4*)&sA[0][r0g][c0g * 8] = pa0;
    *(float4*)&sA[0][r1g][c1g * 8] = pa1;
    *(float4*)&sB[0][r0g][c0g * 8] = pb0;
    *(float4*)&sB[0][r1g][c1g * 8] = pb1;
    __syncthreads();

    for (int st = 0; st < 48; st++) {
        const int cur = st & 1;
        const int nxt = cur ^ 1;
        if (st < 47) {
            const int p = (st + 1) >> 4;
            const int k0 = ((st + 1) & 15) * 32;
            const __nv_bfloat16* __restrict__ Asrc = (p == 1) ? g_hs_lo : g_hs_hi;
            const __nv_bfloat16* __restrict__ Bsrc = (p == 2) ? g_wo_lo : g_wo_hi;
            pa0 = *(const float4*)&Asrc[(size_t)(m0 + r0g) * Hx + k0 + c0g * 8];
            pa1 = *(const float4*)&Asrc[(size_t)(m0 + r1g) * Hx + k0 + c1g * 8];
            pb0 = *(const float4*)&Bsrc[(size_t)(n0 + r0g) * Hx + k0 + c0g * 8];
            pb1 = *(const float4*)&Bsrc[(size_t)(n0 + r1g) * Hx + k0 + c1g * 8];
        }

        const uint32_t aBase = sA_u + cur * bufStride;
        const uint32_t bBase = sB_u + cur * bufStride;
#pragma unroll
        for (int kk = 0; kk < 2; kk++) {
            uint32_t afr[2][4];
#pragma unroll
            for (int mt = 0; mt < 2; mt++)
                ldm_x4(aBase + (a_row + mt * 16) * (OG_PAD * 2) + kk * 32 + a_colb,
                       afr[mt]);
            uint32_t bfr[4][4];
#pragma unroll
            for (int np = 0; np < 4; np++)
                ldm_x4(bBase + (b_row + np * 16) * (OG_PAD * 2) + kk * 32 + b_colb,
                       bfr[np]);
#pragma unroll
            for (int mt = 0; mt < 2; mt++)
#pragma unroll
                for (int nt = 0; nt < 8; nt++)
                    mma_bf16(acc[mt][nt], afr[mt], &bfr[nt >> 1][(nt & 1) * 2]);
        }

        if (st < 47) {
            __syncthreads();
            *(float4*)&sA[nxt][r0g][c0g * 8] = pa0;
            *(float4*)&sA[nxt][r1g][c1g * 8] = pa1;
            *(float4*)&sB[nxt][r0g][c0g * 8] = pb0;
            *(float4*)&sB[nxt][r1g][c1g * 8] = pb1;
            __syncthreads();
        }
    }

    const int gid = lane >> 2;
    const int tig = lane & 3;
#pragma unroll
    for (int mt = 0; mt < 2; mt++) {
        const int mrow0 = m0 + wm * 32 + mt * 16 + gid;
#pragma unroll
        for (int half = 0; half < 2; half++) {
            const int m = mrow0 + half * 8;
            const int s = m >> 8;
            const int b = m & 255;
            float* __restrict__ orow = out + ((size_t)b * Sx + s) * Vx;
#pragma unroll
            for (int nt = 0; nt < 8; nt++) {
                const int n = n0 + wn * 64 + nt * 8 + tig * 2;
                if (n + 1 < Vx) {
                    float2 v;
                    v.x = acc[mt][nt][half * 2 + 0] + bo[n];
                    v.y = acc[mt][nt][half * 2 + 1] + bo[n + 1];
                    *(float2*)&orow[n] = v;
                } else if (n < Vx) {
                    orow[n] = acc[mt][nt][half * 2 + 0] + bo[n];
                }
            }
        }
    }
}

// ---------------------------------------------------------------------------
extern "C" void kernel_launch(void* const* d_in, const int* in_sizes, int n_in,
                              void* d_out, int out_size)
{
    const float* enc   = (const float*)d_in[0];
    const int*   tok   = (const int*)  d_in[1];
    const float* emb   = (const float*)d_in[2];
    const float* W_ih  = (const float*)d_in[3];
    const float* W_hh  = (const float*)d_in[4];
    const float* b_ih  = (const float*)d_in[5];
    const float* b_hh  = (const float*)d_in[6];
    // d_in[7..9]: attn_W, attn_b, v_w -- provably unused (softmax over 1 source pos)
    const float* out_W = (const float*)d_in[10];
    const float* out_b = (const float*)d_in[11];
    float* out = (float*)d_out;

    float *p_emb_proj = nullptr, *p_const = nullptr;
    cudaGetSymbolAddress((void**)&p_emb_proj, g_emb_proj);
    cudaGetSymbolAddress((void**)&p_const, g_const);

    cudaFuncSetAttribute(lstm_persist, cudaFuncAttributeMaxDynamicSharedMemorySize,
                         LP_SMEM);

    // 1) emb_proj[V, 4H] = embedding @ W_ih[:, :E]^T
    {
        dim3 grid(G4H / 64, (Vx + 63) / 64);
        gemm_nt64<<<grid, 256>>>(emb, Ex, W_ih, 2 * Ex, 0,
                                 nullptr, nullptr,
                                 p_emb_proj, G4H, Vx, G4H, Ex);
    }
    // 2) const[B, 4H] = enc @ W_ih[:, E:]^T + b_ih + b_hh
    {
        dim3 grid(G4H / 64, Bx / 64);
        gemm_nt64<<<grid, 256>>>(enc, Ex, W_ih, 2 * Ex, Ex,
                                 b_ih, b_hh,
                                 p_const, G4H, Bx, G4H, Ex);
    }
    // 2b) W_hh -> bf16 hi/lo [u*4+g][k]; out_W -> bf16 hi/lo; reset barrier
    cvt_whh<<<(G4H * 32) / 256, 256>>>(W_hh);
    cvt_wo<<<(VP * Hx) / 1024, 256>>>(out_W);
    zero_bar<<<1, 1>>>();

    // 3) ALL 141 LSTM steps in one persistent tensor-core kernel
    lstm_persist<<<NBLK, 256, LP_SMEM>>>(tok);

    // 4) logits = hs @ out_W^T + out_b  (mma.sync bf16, 3-pass split)
    {
        dim3 grid(VP / 128, Mtot / 128);   // 8 x 282
        out_gemm_mma<<<grid, 256>>>(out_b, out);
    }
}